// round 14
// baseline (speedup 1.0000x reference)
#include <cuda_runtime.h>
#include <cuda_bf16.h>
#include <cstdint>
#include <math.h>

#define NROWS 16384        // B * L = 16 * 1024
#define SEQL  1024
#define SCALE_INV 0.08838834764831845f   // 1/sqrt(128)

// ---------------- persistent scratch ----------------
__device__ float g_x [NROWS*128];
__device__ float g_y [NROWS*128];
__device__ __nv_bfloat16 g_qh [NROWS*128];
__device__ __nv_bfloat16 g_ql [NROWS*128];
__device__ __nv_bfloat16 g_kh [NROWS*128];
__device__ __nv_bfloat16 g_kl [NROWS*128];
__device__ __nv_bfloat16 g_xuh[NROWS*128];
__device__ __nv_bfloat16 g_xul[NROWS*128];
__device__ __nv_bfloat16 g_yuh[NROWS*128];
__device__ __nv_bfloat16 g_yul[NROWS*128];
__device__ float g_vx [NROWS];
__device__ float g_vy [NROWS];
__device__ float g_vxm[NROWS];
__device__ float g_vym[NROWS];
// preconverted weights: 14 matrices of 128x128
//  0:l1_w 1:l2_w  2+4i+{0,1,2,3}: wq(i), wx(i), wk(i), wy(i)
__device__ __align__(16) __nv_bfloat16 g_wbh[14*16384];
__device__ __align__(16) __nv_bfloat16 g_wbl[14*16384];

__device__ __forceinline__ float sigmoidf_fast(float x) {
    return __fdividef(1.f, 1.f + __expf(-x));
}

__device__ __forceinline__ uint32_t smem_u32(const void* p) {
    uint32_t a;
    asm("{ .reg .u64 t; cvta.to.shared.u64 t, %1; cvt.u32.u64 %0, t; }" : "=r"(a) : "l"(p));
    return a;
}

__device__ __forceinline__ uint32_t packbf(__nv_bfloat16 a, __nv_bfloat16 b) {
    __nv_bfloat162 t(a, b);
    return *reinterpret_cast<uint32_t*>(&t);
}

__device__ __forceinline__ void split2(float a, float b, uint32_t& hi, uint32_t& lo) {
    __nv_bfloat16 h0 = __float2bfloat16_rn(a), h1 = __float2bfloat16_rn(b);
    hi = packbf(h0, h1);
    lo = packbf(__float2bfloat16_rn(a - __bfloat162float(h0)),
                __float2bfloat16_rn(b - __bfloat162float(h1)));
}

__device__ __forceinline__ void ldsm_x4(uint32_t r[4], uint32_t addr) {
    asm volatile("ldmatrix.sync.aligned.m8n8.x4.shared.b16 {%0,%1,%2,%3}, [%4];"
                 : "=r"(r[0]), "=r"(r[1]), "=r"(r[2]), "=r"(r[3]) : "r"(addr));
}
__device__ __forceinline__ void ldsm_x4t(uint32_t r[4], uint32_t addr) {
    asm volatile("ldmatrix.sync.aligned.m8n8.x4.trans.shared.b16 {%0,%1,%2,%3}, [%4];"
                 : "=r"(r[0]), "=r"(r[1]), "=r"(r[2]), "=r"(r[3]) : "r"(addr));
}
__device__ __forceinline__ void mma_bf16(float c[4], const uint32_t a[4],
                                         uint32_t b0, uint32_t b1) {
    asm volatile(
        "mma.sync.aligned.m16n8k16.row.col.f32.bf16.bf16.f32 "
        "{%0,%1,%2,%3}, {%4,%5,%6,%7}, {%8,%9}, {%0,%1,%2,%3};"
        : "+f"(c[0]), "+f"(c[1]), "+f"(c[2]), "+f"(c[3])
        : "r"(a[0]), "r"(a[1]), "r"(a[2]), "r"(a[3]), "r"(b0), "r"(b1));
}

__device__ __forceinline__ void cp16(uint32_t saddr, const void* g) {
    asm volatile("cp.async.cg.shared.global [%0], [%1], 16;" :: "r"(saddr), "l"(g));
}
__device__ __forceinline__ void cp_commit() {
    asm volatile("cp.async.commit_group;" ::: "memory");
}
template<int N>
__device__ __forceinline__ void cp_wait() {
    asm volatile("cp.async.wait_group %0;" :: "n"(N) : "memory");
}

// ---- smem geometry ----
#define IROWB 272
#define QTILE (128 * IROWB)      // 34816
#define STILE (64 * IROWB)       // 17408
#define JTILE (32 * IROWB)       // 8704

// interact smem: 128-thr CTA, 64 i-rows, 32-row j-tiles; 2 CTAs/SM
#define O_QH  0
#define O_QL  STILE
#define O_ST  (2 * STILE)        // 34816
#define S_KH  0
#define S_KL  JTILE
#define S_UH  (2 * JTILE)
#define S_UL  (3 * JTILE)
#define S_BS  (4 * JTILE)        // 32 floats
#define STAGE (4 * JTILE + 256)  // 35072
#define O_AS  (O_ST + 2 * STAGE) // 104960
#define I_SMEM (O_AS + 256)      // 105216

// proj / embed smem: 256-thr CTA, 64 X-rows, W time-multiplexed; 2 CTAs/SM
#define P_XH  0
#define P_XL  STILE
#define P_WH  (2 * STILE)        // 128 k-rows
#define P_WL  (P_WH + QTILE)
#define P_SMEM (P_WL + QTILE)    // 104448

// =====================================================================
// prep: convert 14 weight matrices fp32 -> bf16 hi/lo in gmem (once)
// =====================================================================
__global__ __launch_bounds__(256) void prep_w_kernel(
    const float* __restrict__ l1_w, const float* __restrict__ l2_w,
    const float* __restrict__ wq_w, const float* __restrict__ wx_w,
    const float* __restrict__ wk_w, const float* __restrict__ wy_w,
    __nv_bfloat16* __restrict__ WH, __nv_bfloat16* __restrict__ WL) {
    int m = blockIdx.y;
    const float* src;
    if (m == 0) src = l1_w;
    else if (m == 1) src = l2_w;
    else {
        int i = (m - 2) >> 2, r = (m - 2) & 3;
        src = (r == 0 ? wq_w : r == 1 ? wx_w : r == 2 ? wk_w : wy_w) + i * 16384;
    }
    int idx = blockIdx.x * 256 + threadIdx.x;   // 0..8191 (float2 units)
    float2 v = *(const float2*)(src + 2 * idx);
    uint32_t h, l;
    split2(v.x, v.y, h, l);
    *(uint32_t*)(WH + m * 16384 + 2 * idx) = h;
    *(uint32_t*)(WL + m * 16384 + 2 * idx) = l;
}

// =====================================================================
// interact: R13 + single barrier per j-tile (issue after top barrier).
// 128 threads / 4 warps, 64 i-rows, 32-row j-tiles, hoisted Q frags;
// 2 CTAs/SM.
// =====================================================================
__global__ __launch_bounds__(128, 2) void interact_mma_kernel(
    const __nv_bfloat16* __restrict__ qh, const __nv_bfloat16* __restrict__ ql,
    const __nv_bfloat16* __restrict__ kh, const __nv_bfloat16* __restrict__ kl,
    const __nv_bfloat16* __restrict__ xuh, const __nv_bfloat16* __restrict__ xul,
    const __nv_bfloat16* __restrict__ yuh, const __nv_bfloat16* __restrict__ yul,
    const float* __restrict__ vxm, const float* __restrict__ vy,
    const float* __restrict__ vym, const float* __restrict__ vx,
    float* __restrict__ xO, float* __restrict__ yO) {
    extern __shared__ __align__(16) char sm[];
    const int tid  = threadIdx.x;
    const int w    = tid >> 5, lane = tid & 31;
    const int b    = blockIdx.y;
    const int i0   = blockIdx.x * 64;
    const int z    = blockIdx.z;
    const uint32_t sb = smem_u32(sm);
    float* aSs = (float*)(sm + O_AS);

    const __nv_bfloat16* Ah = z ? kh  : qh;
    const __nv_bfloat16* Al = z ? kl  : ql;
    const __nv_bfloat16* Kh = z ? qh  : kh;
    const __nv_bfloat16* Kl = z ? ql  : kl;
    const __nv_bfloat16* Uh = z ? xuh : yuh;
    const __nv_bfloat16* Ul = z ? xul : yul;
    const float* aS = z ? vym : vxm;
    const float* bS = z ? vx  : vy;
    float* Out      = z ? yO  : xO;

    const size_t rowbase = (size_t)(b * SEQL + i0) * 128;

    for (int i = tid; i < 64 * 16; i += 128) {
        int r = i >> 4, c = i & 15;
        uint32_t ro = (uint32_t)(r * IROWB + c * 16);
        size_t go = rowbase + (size_t)r * 128 + c * 8;
        cp16(sb + O_QH + ro, Ah + go);
        cp16(sb + O_QL + ro, Al + go);
    }
    if (tid < 16) cp16(sb + O_AS + tid * 16, aS + b * SEQL + i0 + tid * 4);

#define ISSUE_STAGE(JT, BUF) do { \
        const size_t jb = (size_t)(b * SEQL + (JT) * 32) * 128; \
        uint32_t st = sb + O_ST + (BUF) * STAGE; \
        for (int i = tid; i < 32 * 16; i += 128) { \
            int r = i >> 4, c = i & 15; \
            uint32_t ro = (uint32_t)(r * IROWB + c * 16); \
            size_t go = jb + (size_t)r * 128 + c * 8; \
            cp16(st + S_KH + ro, Kh + go); \
            cp16(st + S_KL + ro, Kl + go); \
            cp16(st + S_UH + ro, Uh + go); \
            cp16(st + S_UL + ro, Ul + go); \
        } \
        if (tid < 8) cp16(st + S_BS + tid * 16, bS + b * SEQL + (JT) * 32 + tid * 4); \
    } while (0)

    ISSUE_STAGE(0, 0);
    cp_commit();

    float oacc[16][4];
#pragma unroll
    for (int n = 0; n < 16; n++)
#pragma unroll
        for (int c = 0; c < 4; c++) oacc[n][c] = 0.f;

    const uint32_t a_row  = 16 * w + (lane & 15);
    const uint32_t a_cadd = (lane & 16) ? 16 : 0;
    const uint32_t b_rsub = (uint32_t)(((lane & 16) ? 8 : 0) + (lane & 7));
    const uint32_t b_cadd = (lane & 8) ? 16 : 0;
    const uint32_t u_radd = (uint32_t)(lane & 15);
    const uint32_t u_cadd = (lane & 16) ? 16 : 0;

    // hoisted Q fragments (filled at jt==0, reused for all j-tiles)
    uint32_t ahr[8][4], alr[8][4];

    for (int jt = 0; jt < 32; jt++) {
        // stage jt was issued before this iteration; wait for it
        cp_wait<0>();
        __syncthreads();   // stage jt visible; all warps past jt-1's reads

        // prefetch stage jt+1 into the other buffer (read last at jt-1; safe)
        if (jt + 1 < 32) {
            ISSUE_STAGE(jt + 1, (jt + 1) & 1);
            cp_commit();
        }

        if (jt == 0) {
#pragma unroll
            for (int kt = 0; kt < 8; kt++) {
                uint32_t aoff = a_row * IROWB + kt * 32 + a_cadd;
                ldsm_x4(ahr[kt], sb + O_QH + aoff);
                ldsm_x4(alr[kt], sb + O_QL + aoff);
            }
        }

        const uint32_t st = sb + O_ST + (jt & 1) * STAGE;
        const float* bSs = (const float*)(sm + O_ST + (jt & 1) * STAGE + S_BS);

        float sacc[4][4];
#pragma unroll
        for (int n = 0; n < 4; n++)
#pragma unroll
            for (int c = 0; c < 4; c++) sacc[n][c] = 0.f;

#pragma unroll
        for (int kt = 0; kt < 8; kt++) {
            uint32_t b0off = b_rsub * IROWB + kt * 32 + b_cadd;
            uint32_t b1off = (16 + b_rsub) * IROWB + kt * 32 + b_cadd;
            uint32_t bh0[4], bl0[4], bh1[4], bl1[4];
            ldsm_x4(bh0, st + S_KH + b0off);
            ldsm_x4(bl0, st + S_KL + b0off);
            ldsm_x4(bh1, st + S_KH + b1off);
            ldsm_x4(bl1, st + S_KL + b1off);
            mma_bf16(sacc[0], ahr[kt], bh0[0], bh0[1]);
            mma_bf16(sacc[1], ahr[kt], bh0[2], bh0[3]);
            mma_bf16(sacc[2], ahr[kt], bh1[0], bh1[1]);
            mma_bf16(sacc[3], ahr[kt], bh1[2], bh1[3]);
            mma_bf16(sacc[0], ahr[kt], bl0[0], bl0[1]);
            mma_bf16(sacc[1], ahr[kt], bl0[2], bl0[3]);
            mma_bf16(sacc[2], ahr[kt], bl1[0], bl1[1]);
            mma_bf16(sacc[3], ahr[kt], bl1[2], bl1[3]);
            mma_bf16(sacc[0], alr[kt], bh0[0], bh0[1]);
            mma_bf16(sacc[1], alr[kt], bh0[2], bh0[3]);
            mma_bf16(sacc[2], alr[kt], bh1[0], bh1[1]);
            mma_bf16(sacc[3], alr[kt], bh1[2], bh1[3]);
        }

        uint32_t ph[4][2], pl[4][2];
#pragma unroll
        for (int n = 0; n < 4; n++) {
            int j0 = 8 * n + 2 * (lane & 3);
            float2 bv = *(const float2*)(bSs + j0);
            float p00 = sigmoidf_fast(sacc[n][0] * SCALE_INV) * bv.x;
            float p01 = sigmoidf_fast(sacc[n][1] * SCALE_INV) * bv.y;
            float p10 = sigmoidf_fast(sacc[n][2] * SCALE_INV) * bv.x;
            float p11 = sigmoidf_fast(sacc[n][3] * SCALE_INV) * bv.y;
            split2(p00, p01, ph[n][0], pl[n][0]);
            split2(p10, p11, ph[n][1], pl[n][1]);
        }

#pragma unroll
        for (int kt = 0; kt < 2; kt++) {
            uint32_t ah[4] = { ph[2*kt][0], ph[2*kt][1], ph[2*kt+1][0], ph[2*kt+1][1] };
            uint32_t al[4] = { pl[2*kt][0], pl[2*kt][1], pl[2*kt+1][0], pl[2*kt+1][1] };
#pragma unroll
            for (int npp = 0; npp < 4; npp++) {
                int np0 = 2 * npp, np1 = 2 * npp + 1;
                uint32_t u0off = (16 * kt + u_radd) * IROWB + np0 * 32 + u_cadd;
                uint32_t u1off = (16 * kt + u_radd) * IROWB + np1 * 32 + u_cadd;
                uint32_t uh0[4], ul0[4], uh1[4], ul1[4];
                ldsm_x4t(uh0, st + S_UH + u0off);
                ldsm_x4t(ul0, st + S_UL + u0off);
                ldsm_x4t(uh1, st + S_UH + u1off);
                ldsm_x4t(ul1, st + S_UL + u1off);
                mma_bf16(oacc[2*np0],   ah, uh0[0], uh0[1]);
                mma_bf16(oacc[2*np0+1], ah, uh0[2], uh0[3]);
                mma_bf16(oacc[2*np1],   ah, uh1[0], uh1[1]);
                mma_bf16(oacc[2*np1+1], ah, uh1[2], uh1[3]);
                mma_bf16(oacc[2*np0],   ah, ul0[0], ul0[1]);
                mma_bf16(oacc[2*np0+1], ah, ul0[2], ul0[3]);
                mma_bf16(oacc[2*np1],   ah, ul1[0], ul1[1]);
                mma_bf16(oacc[2*np1+1], ah, ul1[2], ul1[3]);
                mma_bf16(oacc[2*np0],   al, uh0[0], uh0[1]);
                mma_bf16(oacc[2*np0+1], al, uh0[2], uh0[3]);
                mma_bf16(oacc[2*np1],   al, uh1[0], uh1[1]);
                mma_bf16(oacc[2*np1+1], al, uh1[2], uh1[3]);
            }
        }
    }
#undef ISSUE_STAGE

    __syncthreads();   // all reads of final stage done before writeback reuses nothing (defensive; cheap, once)
    {
        int r0 = 16 * w + (lane >> 2), r1 = r0 + 8;
        float av0 = aSs[r0], av1 = aSs[r1];
        float* Ob = Out + rowbase;
#pragma unroll
        for (int n = 0; n < 16; n++) {
            int d = 8 * n + 2 * (lane & 3);
            float2 o0 = *(float2*)(Ob + (size_t)r0 * 128 + d);
            o0.x += av0 * oacc[n][0];
            o0.y += av0 * oacc[n][1];
            *(float2*)(Ob + (size_t)r0 * 128 + d) = o0;
            float2 o1 = *(float2*)(Ob + (size_t)r1 * 128 + d);
            o1.x += av1 * oacc[n][2];
            o1.y += av1 * oacc[n][3];
            *(float2*)(Ob + (size_t)r1 * 128 + d) = o1;
        }
    }
}

// =====================================================================
// proj (mma) with fused LN; Wq prefetched via cp.async BEFORE the LN
// phase (hidden behind LN/gating/conversion). 2 CTAs/SM.
// =====================================================================
__global__ __launch_bounds__(256, 2) void proj_mma_kernel(
    float* __restrict__ X1, float* __restrict__ X2,
    const float* __restrict__ lng1, const float* __restrict__ lnb1,
    const float* __restrict__ lng2, const float* __restrict__ lnb2,
    const __nv_bfloat16* __restrict__ WqH1, const __nv_bfloat16* __restrict__ WqL1,
    const float* __restrict__ bq1,
    const __nv_bfloat16* __restrict__ WuH1, const __nv_bfloat16* __restrict__ WuL1,
    const float* __restrict__ bu1,
    const float* __restrict__ wv1, const float* __restrict__ bv1,
    const __nv_bfloat16* __restrict__ WqH2, const __nv_bfloat16* __restrict__ WqL2,
    const float* __restrict__ bq2,
    const __nv_bfloat16* __restrict__ WuH2, const __nv_bfloat16* __restrict__ WuL2,
    const float* __restrict__ bu2,
    const float* __restrict__ wv2, const float* __restrict__ bv2,
    const float* __restrict__ mask1, const float* __restrict__ mask2,
    __nv_bfloat16* __restrict__ qh, __nv_bfloat16* __restrict__ ql,
    __nv_bfloat16* __restrict__ xuh, __nv_bfloat16* __restrict__ xul,
    __nv_bfloat16* __restrict__ kh, __nv_bfloat16* __restrict__ kl,
    __nv_bfloat16* __restrict__ yuh, __nv_bfloat16* __restrict__ yul,
    float* __restrict__ vx, float* __restrict__ vxm,
    float* __restrict__ vy, float* __restrict__ vym) {
    extern __shared__ __align__(16) char sm[];
    const int tid = threadIdx.x;
    const int w   = tid >> 5, lane = tid & 31;
    const int row0 = blockIdx.x * 64;
    const int z = blockIdx.y;
    const uint32_t sb = smem_u32(sm);

    float* X = z ? X2 : X1;
    const float* lng = z ? lng2 : lng1;
    const float* lnb = z ? lnb2 : lnb1;
    const __nv_bfloat16* WqH = z ? WqH2 : WqH1;
    const __nv_bfloat16* WqL = z ? WqL2 : WqL1;
    const __nv_bfloat16* WuH = z ? WuH2 : WuH1;
    const __nv_bfloat16* WuL = z ? WuL2 : WuL1;
    const float* bq = z ? bq2 : bq1;
    const float* bu = z ? bu2 : bu1;
    const float* wv = z ? wv2 : wv1;
    const float* bv = z ? bv2 : bv1;
    const float* mask = z ? mask2 : mask1;
    __nv_bfloat16* Qh = z ? kh : qh;
    __nv_bfloat16* Ql = z ? kl : ql;
    __nv_bfloat16* Uh = z ? yuh : xuh;
    __nv_bfloat16* Ul = z ? yul : xul;
    float* Vs  = z ? vy : vx;
    float* Vsm = z ? vym : vxm;

    // prefetch Wq while we do LN (W buffer untouched by LN phase)
    for (int idx = tid; idx < 128 * 16; idx += 256) {
        int r = idx >> 4, c = idx & 15;
        uint32_t ro = (uint32_t)(r * IROWB + c * 16);
        cp16(sb + P_WH + ro, WqH + (size_t)r * 128 + c * 8);
        cp16(sb + P_WL + ro, WqL + (size_t)r * 128 + c * 8);
    }
    cp_commit();

    // ---- fused LN + conversion + gating: warp handles 8 rows ----
    {
        float4 gg  = ((const float4*)lng)[lane];
        float4 bb4 = ((const float4*)lnb)[lane];
        float4 wv4 = ((const float4*)wv)[lane];
        float bv0 = bv[0];
        for (int rr = 0; rr < 8; rr++) {
            int r  = 8 * w + rr;
            int gr = row0 + r;
            float4* Xr = (float4*)(X + (size_t)gr * 128);
            float4 v = Xr[lane];
            float s = v.x + v.y + v.z + v.w;
#pragma unroll
            for (int o = 16; o; o >>= 1) s += __shfl_xor_sync(0xffffffffu, s, o);
            float m = s * (1.f/128.f);
            float d0 = v.x - m, d1 = v.y - m, d2 = v.z - m, d3 = v.w - m;
            float q = d0*d0 + d1*d1 + d2*d2 + d3*d3;
#pragma unroll
            for (int o = 16; o; o >>= 1) q += __shfl_xor_sync(0xffffffffu, q, o);
            float inv = rsqrtf(q * (1.f/128.f) + 1e-5f);
            v.x = d0*inv*gg.x + bb4.x;
            v.y = d1*inv*gg.y + bb4.y;
            v.z = d2*inv*gg.z + bb4.z;
            v.w = d3*inv*gg.w + bb4.w;
            Xr[lane] = v;

            float gs = v.x*wv4.x + v.y*wv4.y + v.z*wv4.z + v.w*wv4.w;
#pragma unroll
            for (int o = 16; o; o >>= 1) gs += __shfl_xor_sync(0xffffffffu, gs, o);
            if (lane == 0) {
                float vv = fmaxf(gs + bv0, 0.f);
                Vs[gr]  = vv;
                Vsm[gr] = vv * mask[gr];
            }

            uint32_t h0, l0, h1, l1;
            split2(v.x, v.y, h0, l0);
            split2(v.z, v.w, h1, l1);
            *(uint2*)(sm + P_XH + (uint32_t)(r * IROWB + lane * 8)) = make_uint2(h0, h1);
            *(uint2*)(sm + P_XL + (uint32_t)(r * IROWB + lane * 8)) = make_uint2(l0, l1);
        }
    }

    const int wr = w >> 1, wc = w & 1;
    const uint32_t a_row  = 16 * wr + (lane & 15);
    const uint32_t a_cadd = (lane & 16) ? 16 : 0;
    const uint32_t u_radd = (uint32_t)(lane & 15);
    const uint32_t u_cadd = (lane & 16) ? 16 : 0;
    const int r0 = 16 * wr + (lane >> 2), r1 = r0 + 8;

    for (int g = 0; g < 2; g++) {
        if (g == 1) {
            __syncthreads();   // all warps done reading Wq before overwrite
            for (int idx = tid; idx < 128 * 16; idx += 256) {
                int r = idx >> 4, c = idx & 15;
                uint32_t ro = (uint32_t)(r * IROWB + c * 16);
                cp16(sb + P_WH + ro, WuH + (size_t)r * 128 + c * 8);
                cp16(sb + P_WL + ro, WuL + (size_t)r * 128 + c * 8);
            }
            cp_commit();
        }
        cp_wait<0>();
        __syncthreads();   // W visible (and X smem on g==0)

        float acc[8][4];
#pragma unroll
        for (int n = 0; n < 8; n++)
#pragma unroll
            for (int c = 0; c < 4; c++) acc[n][c] = 0.f;

#pragma unroll
        for (int kt = 0; kt < 8; kt++) {
            uint32_t aoff = a_row * IROWB + kt * 32 + a_cadd;
            uint32_t ah[4], al[4];
            ldsm_x4(ah, sb + P_XH + aoff);
            ldsm_x4(al, sb + P_XL + aoff);
#pragma unroll
            for (int npp = 0; npp < 2; npp++) {
                int np0 = 2 * npp, np1 = 2 * npp + 1;
                uint32_t b0off = (16 * kt + u_radd) * IROWB + wc * 128 + np0 * 32 + u_cadd;
                uint32_t b1off = (16 * kt + u_radd) * IROWB + wc * 128 + np1 * 32 + u_cadd;
                uint32_t bh0[4], bl0[4], bh1[4], bl1[4];
                ldsm_x4t(bh0, sb + P_WH + b0off);
                ldsm_x4t(bl0, sb + P_WL + b0off);
                ldsm_x4t(bh1, sb + P_WH + b1off);
                ldsm_x4t(bl1, sb + P_WL + b1off);
                mma_bf16(acc[2*np0],   ah, bh0[0], bh0[1]);
                mma_bf16(acc[2*np0+1], ah, bh0[2], bh0[3]);
                mma_bf16(acc[2*np1],   ah, bh1[0], bh1[1]);
                mma_bf16(acc[2*np1+1], ah, bh1[2], bh1[3]);
                mma_bf16(acc[2*np0],   ah, bl0[0], bl0[1]);
                mma_bf16(acc[2*np0+1], ah, bl0[2], bl0[3]);
                mma_bf16(acc[2*np1],   ah, bl1[0], bl1[1]);
                mma_bf16(acc[2*np1+1], ah, bl1[2], bl1[3]);
                mma_bf16(acc[2*np0],   al, bh0[0], bh0[1]);
                mma_bf16(acc[2*np0+1], al, bh0[2], bh0[3]);
                mma_bf16(acc[2*np1],   al, bh1[0], bh1[1]);
                mma_bf16(acc[2*np1+1], al, bh1[2], bh1[3]);
            }
        }

        const float* bias = g ? bu : bq;
        __nv_bfloat16* Oh = g ? Uh : Qh;
        __nv_bfloat16* Ol = g ? Ul : Ql;
#pragma unroll
        for (int n = 0; n < 8; n++) {
            int d = wc * 64 + 8 * n + 2 * (lane & 3);
            float2 bb = *(const float2*)(bias + d);
            float v00 = acc[n][0] + bb.x, v01 = acc[n][1] + bb.y;
            float v10 = acc[n][2] + bb.x, v11 = acc[n][3] + bb.y;
            if (g) {
                v00 = fmaxf(v00, 0.f); v01 = fmaxf(v01, 0.f);
                v10 = fmaxf(v10, 0.f); v11 = fmaxf(v11, 0.f);
            }
            uint32_t h, l;
            split2(v00, v01, h, l);
            *(uint32_t*)(Oh + (size_t)(row0 + r0) * 128 + d) = h;
            *(uint32_t*)(Ol + (size_t)(row0 + r0) * 128 + d) = l;
            split2(v10, v11, h, l);
            *(uint32_t*)(Oh + (size_t)(row0 + r1) * 128 + d) = h;
            *(uint32_t*)(Ol + (size_t)(row0 + r1) * 128 + d) = l;
        }
    }
}

// =====================================================================
// embed (mma): unchanged R13 (64-row CTAs, preconverted W, 2 CTAs/SM)
// =====================================================================
__global__ __launch_bounds__(256, 2) void embed_mma_kernel(
    const float* __restrict__ A1, const float* __restrict__ A2,
    const __nv_bfloat16* __restrict__ WHb, const __nv_bfloat16* __restrict__ WLb,
    const float* __restrict__ b1, const float* __restrict__ b2,
    float* __restrict__ out1, float* __restrict__ out2) {
    extern __shared__ __align__(16) char sm[];
    const int tid = threadIdx.x;
    const int w   = tid >> 5, lane = tid & 31;
    const int row0 = blockIdx.x * 64;
    const int z = blockIdx.y;
    const uint32_t sb = smem_u32(sm);

    const float* A = z ? A2 : A1;
    const __nv_bfloat16* WH = WHb + z * 16384;
    const __nv_bfloat16* WL = WLb + z * 16384;
    const float* bias = z ? b2 : b1;
    float* out = z ? out2 : out1;

    for (int idx = tid; idx < 128 * 16; idx += 256) {
        int r = idx >> 4, c = idx & 15;
        uint32_t ro = (uint32_t)(r * IROWB + c * 16);
        cp16(sb + P_WH + ro, WH + (size_t)r * 128 + c * 8);
        cp16(sb + P_WL + ro, WL + (size_t)r * 128 + c * 8);
    }
    cp_commit();
    for (int idx = tid; idx < 64 * 32; idx += 256) {
        int r = idx >> 5, cq = idx & 31;
        uint32_t off = (uint32_t)(r * IROWB + cq * 8);
        uint32_t h0, l0, h1, l1;
        float4 av = *(const float4*)(A + (size_t)(row0 + r) * 128 + cq * 4);
        split2(av.x, av.y, h0, l0);
        split2(av.z, av.w, h1, l1);
        *(uint2*)(sm + P_XH + off) = make_uint2(h0, h1);
        *(uint2*)(sm + P_XL + off) = make_uint2(l0, l1);
    }
    cp_wait<0>();
    __syncthreads();

    const int wr = w >> 1, wc = w & 1;
    const uint32_t a_row  = 16 * wr + (lane & 15);
    const uint32_t a_cadd = (lane & 16) ? 16 : 0;
    const uint32_t u_radd = (uint32_t)(lane & 15);
    const uint32_t u_cadd = (lane & 16) ? 16 : 0;
    const int r0 = 16 * wr + (lane >> 2), r1 = r0 + 8;

    float acc[8][4];
#pragma unroll
    for (int n = 0; n < 8; n++)
#pragma unroll
        for (int c = 0; c < 4; c++) acc[n][c] = 0.f;

#pragma unroll
    for (int kt = 0; kt < 8; kt++) {
        uint32_t aoff = a_row * IROWB + kt * 32 + a_cadd;
        uint32_t ah[4], al[4];
        ldsm_x4(ah, sb + P_XH + aoff);
        ldsm_x4(al, sb + P_XL + aoff);
#pragma unroll
        for (int npp = 0; npp < 2; npp++) {
            int np0 = 2 * npp, np1 = 2 * npp + 1;
            uint32_t b0off = (16 * kt + u_radd) * IROWB + wc * 128 + np0 * 32 + u_cadd;
            uint32_t b1off = (16 * kt + u_radd) * IROWB + wc * 128 + np1 * 32 + u_cadd;
            uint32_t bh0[4], bl0[4], bh1[4], bl1[4];
            ldsm_x4t(bh0, sb + P_WH + b0off);
            ldsm_x4t(bl0, sb + P_WL + b0off);
            ldsm_x4t(bh1, sb + P_WH + b1off);
            ldsm_x4t(bl1, sb + P_WL + b1off);
            mma_bf16(acc[2*np0],   ah, bh0[0], bh0[1]);
            mma_bf16(acc[2*np0+1], ah, bh0[2], bh0[3]);
            mma_bf16(acc[2*np1],   ah, bh1[0], bh1[1]);
            mma_bf16(acc[2*np1+1], ah, bh1[2], bh1[3]);
            mma_bf16(acc[2*np0],   ah, bl0[0], bl0[1]);
            mma_bf16(acc[2*np0+1], ah, bl0[2], bl0[3]);
            mma_bf16(acc[2*np1],   ah, bl1[0], bl1[1]);
            mma_bf16(acc[2*np1+1], ah, bl1[2], bl1[3]);
            mma_bf16(acc[2*np0],   al, bh0[0], bh0[1]);
            mma_bf16(acc[2*np0+1], al, bh0[2], bh0[3]);
            mma_bf16(acc[2*np1],   al, bh1[0], bh1[1]);
            mma_bf16(acc[2*np1+1], al, bh1[2], bh1[3]);
        }
    }

#pragma unroll
    for (int n = 0; n < 8; n++) {
        int d = wc * 64 + 8 * n + 2 * (lane & 3);
        float2 bb = *(const float2*)(bias + d);
        float2 o0, o1;
        o0.x = fmaxf(acc[n][0] + bb.x, 0.f);
        o0.y = fmaxf(acc[n][1] + bb.y, 0.f);
        o1.x = fmaxf(acc[n][2] + bb.x, 0.f);
        o1.y = fmaxf(acc[n][3] + bb.y, 0.f);
        *(float2*)(out + (size_t)(row0 + r0) * 128 + d) = o0;
        *(float2*)(out + (size_t)(row0 + r1) * 128 + d) = o1;
    }
}

__device__ __forceinline__ float blk_reduce(float v, float* red, bool ismax) {
#pragma unroll
    for (int o = 16; o; o >>= 1) {
        float t = __shfl_xor_sync(0xffffffffu, v, o);
        v = ismax ? fmaxf(v, t) : v + t;
    }
    if ((threadIdx.x & 31) == 0) red[threadIdx.x >> 5] = v;
    __syncthreads();
    float r = red[0];
#pragma unroll
    for (int i = 1; i < 8; i++) r = ismax ? fmaxf(r, red[i]) : r + red[i];
    __syncthreads();
    return r;
}

__global__ __launch_bounds__(256) void pool_head_kernel(
    const float* __restrict__ Xg, const float* __restrict__ Yg,
    const float* __restrict__ fc_w, const float* __restrict__ fc_b,
    const float* __restrict__ out_w, const float* __restrict__ out_b,
    float* __restrict__ out) {
    __shared__ float w[1024];
    __shared__ float red[8];
    __shared__ float pp[256];
    __shared__ float xp[128];
    __shared__ float yp[128];
    const int tid = threadIdx.x;
    const int b   = blockIdx.x;

    for (int s = 0; s < 2; s++) {
        const float* S = (s ? Yg : Xg) + (size_t)b * SEQL * 128;
        float* dst = s ? yp : xp;
        for (int l = tid; l < SEQL; l += 256) {
            const float4* row = (const float4*)(S + (size_t)l*128);
            float acc = 0.f;
#pragma unroll
            for (int c = 0; c < 32; c++) {
                float4 v = row[c];
                acc += v.x*v.x + v.y*v.y + v.z*v.z + v.w*v.w;
            }
            w[l] = sqrtf(acc);
        }
        __syncthreads();
        float lm = -1e30f;
        for (int l = tid; l < SEQL; l += 256) lm = fmaxf(lm, w[l]);
        float mx = blk_reduce(lm, red, true);
        float ls = 0.f;
        for (int l = tid; l < SEQL; l += 256) { float e = expf(w[l] - mx); w[l] = e; ls += e; }
        float tot = blk_reduce(ls, red, false);
        float inv = 1.f / tot;

        int d = tid & 127, halfi = tid >> 7;
        float p = 0.f;
        for (int l = halfi; l < SEQL; l += 2) p += S[(size_t)l*128 + d] * w[l];
        pp[halfi*128 + d] = p;
        __syncthreads();
        if (tid < 128) dst[tid] = (pp[tid] + pp[128 + tid]) * inv;
        __syncthreads();
    }

    float h = 0.f;
    if (tid < 128) {
        h = fc_b[tid];
        for (int k2 = 0; k2 < 128; k2++) h += xp[k2] * fc_w[k2*128 + tid];
        for (int k2 = 0; k2 < 128; k2++) h += yp[k2] * fc_w[(128 + k2)*128 + tid];
        h = fmaxf(h, 0.f) * out_w[tid];
    }
    float tot = blk_reduce(h, red, false);
    if (tid == 0) out[b] = 1.f / (1.f + expf(-(tot + out_b[0])));
}

// ---------------- launch ----------------
extern "C" void kernel_launch(void* const* d_in, const int* in_sizes, int n_in,
                              void* d_out, int out_size) {
    (void)in_sizes; (void)n_in; (void)out_size;
    const float* seq1  = (const float*)d_in[0];
    const float* seq2  = (const float*)d_in[1];
    const float* mask1 = (const float*)d_in[2];
    const float* mask2 = (const float*)d_in[3];
    const float* l1_w  = (const float*)d_in[4];
    const float* l1_b  = (const float*)d_in[5];
    const float* l2_w  = (const float*)d_in[6];
    const float* l2_b  = (const float*)d_in[7];
    const float* ln1_g = (const float*)d_in[8];
    const float* ln1_b = (const float*)d_in[9];
    const float* ln2_g = (const float*)d_in[10];
    const float* ln2_b = (const float*)d_in[11];
    const float* wq_w  = (const float*)d_in[12];
    const float* wq_b  = (const float*)d_in[13];
    const float* wk_w  = (const float*)d_in[14];
    const float* wk_b  = (const float*)d_in[15];
    const float* wvx_w = (const float*)d_in[16];
    const float* wvx_b = (const float*)d_in[17];
    const float* wvy_w = (const float*)d_in[18];
    const float* wvy_b = (const float*)d_in[19];
    const float* wx_w  = (const float*)d_in[20];
    const float* wx_b  = (const float*)d_in[21];
    const float* wy_w  = (const float*)d_in[22];
    const float* wy_b  = (const float*)d_in[23];
    const float* fc_w  = (const float*)d_in[24];
    const float* fc_b  = (const float*)d_in[25];
    const float* out_w = (const float*)d_in[26];
    const float* out_b = (const float*)d_in[27];

    float *x, *y, *vx, *vy, *vxm, *vym;
    __nv_bfloat16 *qh, *ql, *kh, *kl, *xuh, *xul, *yuh, *yul, *wbh, *wbl;
    cudaGetSymbolAddress((void**)&x,   g_x);
    cudaGetSymbolAddress((void**)&y,   g_y);
    cudaGetSymbolAddress((void**)&qh,  g_qh);
    cudaGetSymbolAddress((void**)&ql,  g_ql);
    cudaGetSymbolAddress((void**)&kh,  g_kh);
    cudaGetSymbolAddress((void**)&kl,  g_kl);
    cudaGetSymbolAddress((void**)&xuh, g_xuh);
    cudaGetSymbolAddress((void**)&xul, g_xul);
    cudaGetSymbolAddress((void**)&yuh, g_yuh);
    cudaGetSymbolAddress((void**)&yul, g_yul);
    cudaGetSymbolAddress((void**)&vx,  g_vx);
    cudaGetSymbolAddress((void**)&vy,  g_vy);
    cudaGetSymbolAddress((void**)&vxm, g_vxm);
    cudaGetSymbolAddress((void**)&vym, g_vym);
    cudaGetSymbolAddress((void**)&wbh, g_wbh);
    cudaGetSymbolAddress((void**)&wbl, g_wbl);

    cudaFuncSetAttribute(embed_mma_kernel,    cudaFuncAttributeMaxDynamicSharedMemorySize, P_SMEM);
    cudaFuncSetAttribute(proj_mma_kernel,     cudaFuncAttributeMaxDynamicSharedMemorySize, P_SMEM);
    cudaFuncSetAttribute(interact_mma_kernel, cudaFuncAttributeMaxDynamicSharedMemorySize, I_SMEM);

    prep_w_kernel<<<dim3(32, 14), 256>>>(l1_w, l2_w, wq_w, wx_w, wk_w, wy_w, wbh, wbl);

    embed_mma_kernel<<<dim3(256, 2), 256, P_SMEM>>>(seq1, seq2, wbh, wbl,
                                                    l1_b, l2_b, x, y);

    for (int i = 0; i < 3; i++) {
        int base = 2 + i * 4;
        proj_mma_kernel<<<dim3(256, 2), 256, P_SMEM>>>(
            x, y,
            ln1_g + i*128, ln1_b + i*128, ln2_g + i*128, ln2_b + i*128,
            wbh + (base+0)*16384, wbl + (base+0)*16384, wq_b + i*128,
            wbh + (base+1)*16384, wbl + (base+1)*16384, wx_b + i*128,
            wvx_w + i*128, wvx_b + i,
            wbh + (base+2)*16384, wbl + (base+2)*16384, wk_b + i*128,
            wbh + (base+3)*16384, wbl + (base+3)*16384, wy_b + i*128,
            wvy_w + i*128, wvy_b + i,
            mask1, mask2,
            qh, ql, xuh, xul, kh, kl, yuh, yul,
            vx, vxm, vy, vym);
        interact_mma_kernel<<<dim3(16, 16, 2), 128, I_SMEM>>>(
            qh, ql, kh, kl, xuh, xul, yuh, yul, vxm, vy, vym, vx, x, y);
    }
    pool_head_kernel<<<16, 256>>>(x, y, fc_w, fc_b, out_w, out_b, (float*)d_out);
}

// round 15
// speedup vs baseline: 1.1488x; 1.1488x over previous
#include <cuda_runtime.h>
#include <cuda_bf16.h>
#include <cstdint>
#include <math.h>

#define NROWS 16384        // B * L = 16 * 1024
#define SEQL  1024
#define SCALE_INV 0.08838834764831845f   // 1/sqrt(128)

// ---------------- persistent scratch ----------------
__device__ float g_x [NROWS*128];
__device__ float g_y [NROWS*128];
__device__ __nv_bfloat16 g_qh [NROWS*128];
__device__ __nv_bfloat16 g_ql [NROWS*128];
__device__ __nv_bfloat16 g_kh [NROWS*128];
__device__ __nv_bfloat16 g_kl [NROWS*128];
__device__ __nv_bfloat16 g_xuh[NROWS*128];
__device__ __nv_bfloat16 g_xul[NROWS*128];
__device__ __nv_bfloat16 g_yuh[NROWS*128];
__device__ __nv_bfloat16 g_yul[NROWS*128];
__device__ float g_vx [NROWS];
__device__ float g_vy [NROWS];
__device__ float g_vxm[NROWS];
__device__ float g_vym[NROWS];
__device__ float g_pool[2*16*128];
// preconverted weights: 14 matrices of 128x128
//  0:l1_w 1:l2_w  2+4i+{0,1,2,3}: wq(i), wx(i), wk(i), wy(i)
__device__ __align__(16) __nv_bfloat16 g_wbh[14*16384];
__device__ __align__(16) __nv_bfloat16 g_wbl[14*16384];

__device__ __forceinline__ float sigmoidf_fast(float x) {
    return __fdividef(1.f, 1.f + __expf(-x));
}

__device__ __forceinline__ uint32_t smem_u32(const void* p) {
    uint32_t a;
    asm("{ .reg .u64 t; cvta.to.shared.u64 t, %1; cvt.u32.u64 %0, t; }" : "=r"(a) : "l"(p));
    return a;
}

__device__ __forceinline__ uint32_t packbf(__nv_bfloat16 a, __nv_bfloat16 b) {
    __nv_bfloat162 t(a, b);
    return *reinterpret_cast<uint32_t*>(&t);
}

__device__ __forceinline__ void split2(float a, float b, uint32_t& hi, uint32_t& lo) {
    __nv_bfloat16 h0 = __float2bfloat16_rn(a), h1 = __float2bfloat16_rn(b);
    hi = packbf(h0, h1);
    lo = packbf(__float2bfloat16_rn(a - __bfloat162float(h0)),
                __float2bfloat16_rn(b - __bfloat162float(h1)));
}

__device__ __forceinline__ void ldsm_x4(uint32_t r[4], uint32_t addr) {
    asm volatile("ldmatrix.sync.aligned.m8n8.x4.shared.b16 {%0,%1,%2,%3}, [%4];"
                 : "=r"(r[0]), "=r"(r[1]), "=r"(r[2]), "=r"(r[3]) : "r"(addr));
}
__device__ __forceinline__ void ldsm_x4t(uint32_t r[4], uint32_t addr) {
    asm volatile("ldmatrix.sync.aligned.m8n8.x4.trans.shared.b16 {%0,%1,%2,%3}, [%4];"
                 : "=r"(r[0]), "=r"(r[1]), "=r"(r[2]), "=r"(r[3]) : "r"(addr));
}
__device__ __forceinline__ void mma_bf16(float c[4], const uint32_t a[4],
                                         uint32_t b0, uint32_t b1) {
    asm volatile(
        "mma.sync.aligned.m16n8k16.row.col.f32.bf16.bf16.f32 "
        "{%0,%1,%2,%3}, {%4,%5,%6,%7}, {%8,%9}, {%0,%1,%2,%3};"
        : "+f"(c[0]), "+f"(c[1]), "+f"(c[2]), "+f"(c[3])
        : "r"(a[0]), "r"(a[1]), "r"(a[2]), "r"(a[3]), "r"(b0), "r"(b1));
}

__device__ __forceinline__ void cp16(uint32_t saddr, const void* g) {
    asm volatile("cp.async.cg.shared.global [%0], [%1], 16;" :: "r"(saddr), "l"(g));
}
__device__ __forceinline__ void cp_commit() {
    asm volatile("cp.async.commit_group;" ::: "memory");
}
template<int N>
__device__ __forceinline__ void cp_wait() {
    asm volatile("cp.async.wait_group %0;" :: "n"(N) : "memory");
}

// ---- smem geometry ----
#define IROWB 272
#define QTILE (128 * IROWB)      // 34816
#define STILE (64 * IROWB)       // 17408
#define JTILE (32 * IROWB)       // 8704

// interact smem: 128-thr CTA, 64 i-rows, 32-row j-tiles; 2 CTAs/SM
#define O_QH  0
#define O_QL  STILE
#define O_ST  (2 * STILE)        // 34816
#define S_KH  0
#define S_KL  JTILE
#define S_UH  (2 * JTILE)
#define S_UL  (3 * JTILE)
#define S_BS  (4 * JTILE)        // 32 floats
#define STAGE (4 * JTILE + 256)  // 35072
#define O_AS  (O_ST + 2 * STAGE) // 104960
#define I_SMEM (O_AS + 256)      // 105216

// proj / embed smem: 256-thr CTA, 64 X-rows, W time-multiplexed; 2 CTAs/SM
#define P_XH  0
#define P_XL  STILE
#define P_WH  (2 * STILE)        // 128 k-rows
#define P_WL  (P_WH + QTILE)
#define P_SMEM (P_WL + QTILE)    // 104448

// =====================================================================
// prep: convert 14 weight matrices fp32 -> bf16 hi/lo in gmem (once)
// =====================================================================
__global__ __launch_bounds__(256) void prep_w_kernel(
    const float* __restrict__ l1_w, const float* __restrict__ l2_w,
    const float* __restrict__ wq_w, const float* __restrict__ wx_w,
    const float* __restrict__ wk_w, const float* __restrict__ wy_w,
    __nv_bfloat16* __restrict__ WH, __nv_bfloat16* __restrict__ WL) {
    int m = blockIdx.y;
    const float* src;
    if (m == 0) src = l1_w;
    else if (m == 1) src = l2_w;
    else {
        int i = (m - 2) >> 2, r = (m - 2) & 3;
        src = (r == 0 ? wq_w : r == 1 ? wx_w : r == 2 ? wk_w : wy_w) + i * 16384;
    }
    int idx = blockIdx.x * 256 + threadIdx.x;
    float2 v = *(const float2*)(src + 2 * idx);
    uint32_t h, l;
    split2(v.x, v.y, h, l);
    *(uint32_t*)(WH + m * 16384 + 2 * idx) = h;
    *(uint32_t*)(WL + m * 16384 + 2 * idx) = l;
}

// =====================================================================
// interact: R13 VERBATIM (two barriers per j-tile, hoisted Q frags).
// 128 threads / 4 warps, 64 i-rows, 32-row j-tiles; 2 CTAs/SM.
// =====================================================================
__global__ __launch_bounds__(128, 2) void interact_mma_kernel(
    const __nv_bfloat16* __restrict__ qh, const __nv_bfloat16* __restrict__ ql,
    const __nv_bfloat16* __restrict__ kh, const __nv_bfloat16* __restrict__ kl,
    const __nv_bfloat16* __restrict__ xuh, const __nv_bfloat16* __restrict__ xul,
    const __nv_bfloat16* __restrict__ yuh, const __nv_bfloat16* __restrict__ yul,
    const float* __restrict__ vxm, const float* __restrict__ vy,
    const float* __restrict__ vym, const float* __restrict__ vx,
    float* __restrict__ xO, float* __restrict__ yO) {
    extern __shared__ __align__(16) char sm[];
    const int tid  = threadIdx.x;
    const int w    = tid >> 5, lane = tid & 31;
    const int b    = blockIdx.y;
    const int i0   = blockIdx.x * 64;
    const int z    = blockIdx.z;
    const uint32_t sb = smem_u32(sm);
    float* aSs = (float*)(sm + O_AS);

    const __nv_bfloat16* Ah = z ? kh  : qh;
    const __nv_bfloat16* Al = z ? kl  : ql;
    const __nv_bfloat16* Kh = z ? qh  : kh;
    const __nv_bfloat16* Kl = z ? ql  : kl;
    const __nv_bfloat16* Uh = z ? xuh : yuh;
    const __nv_bfloat16* Ul = z ? xul : yul;
    const float* aS = z ? vym : vxm;
    const float* bS = z ? vx  : vy;
    float* Out      = z ? yO  : xO;

    const size_t rowbase = (size_t)(b * SEQL + i0) * 128;

    for (int i = tid; i < 64 * 16; i += 128) {
        int r = i >> 4, c = i & 15;
        uint32_t ro = (uint32_t)(r * IROWB + c * 16);
        size_t go = rowbase + (size_t)r * 128 + c * 8;
        cp16(sb + O_QH + ro, Ah + go);
        cp16(sb + O_QL + ro, Al + go);
    }
    if (tid < 16) cp16(sb + O_AS + tid * 16, aS + b * SEQL + i0 + tid * 4);

#define ISSUE_STAGE(JT, BUF) do { \
        const size_t jb = (size_t)(b * SEQL + (JT) * 32) * 128; \
        uint32_t st = sb + O_ST + (BUF) * STAGE; \
        for (int i = tid; i < 32 * 16; i += 128) { \
            int r = i >> 4, c = i & 15; \
            uint32_t ro = (uint32_t)(r * IROWB + c * 16); \
            size_t go = jb + (size_t)r * 128 + c * 8; \
            cp16(st + S_KH + ro, Kh + go); \
            cp16(st + S_KL + ro, Kl + go); \
            cp16(st + S_UH + ro, Uh + go); \
            cp16(st + S_UL + ro, Ul + go); \
        } \
        if (tid < 8) cp16(st + S_BS + tid * 16, bS + b * SEQL + (JT) * 32 + tid * 4); \
    } while (0)

    ISSUE_STAGE(0, 0);
    cp_commit();

    float oacc[16][4];
#pragma unroll
    for (int n = 0; n < 16; n++)
#pragma unroll
        for (int c = 0; c < 4; c++) oacc[n][c] = 0.f;

    const uint32_t a_row  = 16 * w + (lane & 15);
    const uint32_t a_cadd = (lane & 16) ? 16 : 0;
    const uint32_t b_rsub = (uint32_t)(((lane & 16) ? 8 : 0) + (lane & 7));
    const uint32_t b_cadd = (lane & 8) ? 16 : 0;
    const uint32_t u_radd = (uint32_t)(lane & 15);
    const uint32_t u_cadd = (lane & 16) ? 16 : 0;

    uint32_t ahr[8][4], alr[8][4];

    for (int jt = 0; jt < 32; jt++) {
        if (jt + 1 < 32) {
            ISSUE_STAGE(jt + 1, (jt + 1) & 1);
            cp_commit();
            cp_wait<1>();
        } else {
            cp_wait<0>();
        }
        __syncthreads();

        if (jt == 0) {
#pragma unroll
            for (int kt = 0; kt < 8; kt++) {
                uint32_t aoff = a_row * IROWB + kt * 32 + a_cadd;
                ldsm_x4(ahr[kt], sb + O_QH + aoff);
                ldsm_x4(alr[kt], sb + O_QL + aoff);
            }
        }

        const uint32_t st = sb + O_ST + (jt & 1) * STAGE;
        const float* bSs = (const float*)(sm + O_ST + (jt & 1) * STAGE + S_BS);

        float sacc[4][4];
#pragma unroll
        for (int n = 0; n < 4; n++)
#pragma unroll
            for (int c = 0; c < 4; c++) sacc[n][c] = 0.f;

#pragma unroll
        for (int kt = 0; kt < 8; kt++) {
            uint32_t b0off = b_rsub * IROWB + kt * 32 + b_cadd;
            uint32_t b1off = (16 + b_rsub) * IROWB + kt * 32 + b_cadd;
            uint32_t bh0[4], bl0[4], bh1[4], bl1[4];
            ldsm_x4(bh0, st + S_KH + b0off);
            ldsm_x4(bl0, st + S_KL + b0off);
            ldsm_x4(bh1, st + S_KH + b1off);
            ldsm_x4(bl1, st + S_KL + b1off);
            mma_bf16(sacc[0], ahr[kt], bh0[0], bh0[1]);
            mma_bf16(sacc[1], ahr[kt], bh0[2], bh0[3]);
            mma_bf16(sacc[2], ahr[kt], bh1[0], bh1[1]);
            mma_bf16(sacc[3], ahr[kt], bh1[2], bh1[3]);
            mma_bf16(sacc[0], ahr[kt], bl0[0], bl0[1]);
            mma_bf16(sacc[1], ahr[kt], bl0[2], bl0[3]);
            mma_bf16(sacc[2], ahr[kt], bl1[0], bl1[1]);
            mma_bf16(sacc[3], ahr[kt], bl1[2], bl1[3]);
            mma_bf16(sacc[0], alr[kt], bh0[0], bh0[1]);
            mma_bf16(sacc[1], alr[kt], bh0[2], bh0[3]);
            mma_bf16(sacc[2], alr[kt], bh1[0], bh1[1]);
            mma_bf16(sacc[3], alr[kt], bh1[2], bh1[3]);
        }

        uint32_t ph[4][2], pl[4][2];
#pragma unroll
        for (int n = 0; n < 4; n++) {
            int j0 = 8 * n + 2 * (lane & 3);
            float2 bv = *(const float2*)(bSs + j0);
            float p00 = sigmoidf_fast(sacc[n][0] * SCALE_INV) * bv.x;
            float p01 = sigmoidf_fast(sacc[n][1] * SCALE_INV) * bv.y;
            float p10 = sigmoidf_fast(sacc[n][2] * SCALE_INV) * bv.x;
            float p11 = sigmoidf_fast(sacc[n][3] * SCALE_INV) * bv.y;
            split2(p00, p01, ph[n][0], pl[n][0]);
            split2(p10, p11, ph[n][1], pl[n][1]);
        }

#pragma unroll
        for (int kt = 0; kt < 2; kt++) {
            uint32_t ah[4] = { ph[2*kt][0], ph[2*kt][1], ph[2*kt+1][0], ph[2*kt+1][1] };
            uint32_t al[4] = { pl[2*kt][0], pl[2*kt][1], pl[2*kt+1][0], pl[2*kt+1][1] };
#pragma unroll
            for (int npp = 0; npp < 4; npp++) {
                int np0 = 2 * npp, np1 = 2 * npp + 1;
                uint32_t u0off = (16 * kt + u_radd) * IROWB + np0 * 32 + u_cadd;
                uint32_t u1off = (16 * kt + u_radd) * IROWB + np1 * 32 + u_cadd;
                uint32_t uh0[4], ul0[4], uh1[4], ul1[4];
                ldsm_x4t(uh0, st + S_UH + u0off);
                ldsm_x4t(ul0, st + S_UL + u0off);
                ldsm_x4t(uh1, st + S_UH + u1off);
                ldsm_x4t(ul1, st + S_UL + u1off);
                mma_bf16(oacc[2*np0],   ah, uh0[0], uh0[1]);
                mma_bf16(oacc[2*np0+1], ah, uh0[2], uh0[3]);
                mma_bf16(oacc[2*np1],   ah, uh1[0], uh1[1]);
                mma_bf16(oacc[2*np1+1], ah, uh1[2], uh1[3]);
                mma_bf16(oacc[2*np0],   ah, ul0[0], ul0[1]);
                mma_bf16(oacc[2*np0+1], ah, ul0[2], ul0[3]);
                mma_bf16(oacc[2*np1],   ah, ul1[0], ul1[1]);
                mma_bf16(oacc[2*np1+1], ah, ul1[2], ul1[3]);
                mma_bf16(oacc[2*np0],   al, uh0[0], uh0[1]);
                mma_bf16(oacc[2*np0+1], al, uh0[2], uh0[3]);
                mma_bf16(oacc[2*np1],   al, uh1[0], uh1[1]);
                mma_bf16(oacc[2*np1+1], al, uh1[2], uh1[3]);
            }
        }
        __syncthreads();
    }
#undef ISSUE_STAGE

    {
        int r0 = 16 * w + (lane >> 2), r1 = r0 + 8;
        float av0 = aSs[r0], av1 = aSs[r1];
        float* Ob = Out + rowbase;
#pragma unroll
        for (int n = 0; n < 16; n++) {
            int d = 8 * n + 2 * (lane & 3);
            float2 o0 = *(float2*)(Ob + (size_t)r0 * 128 + d);
            o0.x += av0 * oacc[n][0];
            o0.y += av0 * oacc[n][1];
            *(float2*)(Ob + (size_t)r0 * 128 + d) = o0;
            float2 o1 = *(float2*)(Ob + (size_t)r1 * 128 + d);
            o1.x += av1 * oacc[n][2];
            o1.y += av1 * oacc[n][3];
            *(float2*)(Ob + (size_t)r1 * 128 + d) = o1;
        }
    }
}

// =====================================================================
// proj (mma) with fused LN; Wq prefetched before the LN phase. 2 CTAs/SM.
// =====================================================================
__global__ __launch_bounds__(256, 2) void proj_mma_kernel(
    float* __restrict__ X1, float* __restrict__ X2,
    const float* __restrict__ lng1, const float* __restrict__ lnb1,
    const float* __restrict__ lng2, const float* __restrict__ lnb2,
    const __nv_bfloat16* __restrict__ WqH1, const __nv_bfloat16* __restrict__ WqL1,
    const float* __restrict__ bq1,
    const __nv_bfloat16* __restrict__ WuH1, const __nv_bfloat16* __restrict__ WuL1,
    const float* __restrict__ bu1,
    const float* __restrict__ wv1, const float* __restrict__ bv1,
    const __nv_bfloat16* __restrict__ WqH2, const __nv_bfloat16* __restrict__ WqL2,
    const float* __restrict__ bq2,
    const __nv_bfloat16* __restrict__ WuH2, const __nv_bfloat16* __restrict__ WuL2,
    const float* __restrict__ bu2,
    const float* __restrict__ wv2, const float* __restrict__ bv2,
    const float* __restrict__ mask1, const float* __restrict__ mask2,
    __nv_bfloat16* __restrict__ qh, __nv_bfloat16* __restrict__ ql,
    __nv_bfloat16* __restrict__ xuh, __nv_bfloat16* __restrict__ xul,
    __nv_bfloat16* __restrict__ kh, __nv_bfloat16* __restrict__ kl,
    __nv_bfloat16* __restrict__ yuh, __nv_bfloat16* __restrict__ yul,
    float* __restrict__ vx, float* __restrict__ vxm,
    float* __restrict__ vy, float* __restrict__ vym) {
    extern __shared__ __align__(16) char sm[];
    const int tid = threadIdx.x;
    const int w   = tid >> 5, lane = tid & 31;
    const int row0 = blockIdx.x * 64;
    const int z = blockIdx.y;
    const uint32_t sb = smem_u32(sm);

    float* X = z ? X2 : X1;
    const float* lng = z ? lng2 : lng1;
    const float* lnb = z ? lnb2 : lnb1;
    const __nv_bfloat16* WqH = z ? WqH2 : WqH1;
    const __nv_bfloat16* WqL = z ? WqL2 : WqL1;
    const __nv_bfloat16* WuH = z ? WuH2 : WuH1;
    const __nv_bfloat16* WuL = z ? WuL2 : WuL1;
    const float* bq = z ? bq2 : bq1;
    const float* bu = z ? bu2 : bu1;
    const float* wv = z ? wv2 : wv1;
    const float* bv = z ? bv2 : bv1;
    const float* mask = z ? mask2 : mask1;
    __nv_bfloat16* Qh = z ? kh : qh;
    __nv_bfloat16* Ql = z ? kl : ql;
    __nv_bfloat16* Uh = z ? yuh : xuh;
    __nv_bfloat16* Ul = z ? yul : xul;
    float* Vs  = z ? vy : vx;
    float* Vsm = z ? vym : vxm;

    // prefetch Wq while we do LN (W buffer untouched by LN phase)
    for (int idx = tid; idx < 128 * 16; idx += 256) {
        int r = idx >> 4, c = idx & 15;
        uint32_t ro = (uint32_t)(r * IROWB + c * 16);
        cp16(sb + P_WH + ro, WqH + (size_t)r * 128 + c * 8);
        cp16(sb + P_WL + ro, WqL + (size_t)r * 128 + c * 8);
    }
    cp_commit();

    // ---- fused LN + conversion + gating: warp handles 8 rows ----
    {
        float4 gg  = ((const float4*)lng)[lane];
        float4 bb4 = ((const float4*)lnb)[lane];
        float4 wv4 = ((const float4*)wv)[lane];
        float bv0 = bv[0];
        for (int rr = 0; rr < 8; rr++) {
            int r  = 8 * w + rr;
            int gr = row0 + r;
            float4* Xr = (float4*)(X + (size_t)gr * 128);
            float4 v = Xr[lane];
            float s = v.x + v.y + v.z + v.w;
#pragma unroll
            for (int o = 16; o; o >>= 1) s += __shfl_xor_sync(0xffffffffu, s, o);
            float m = s * (1.f/128.f);
            float d0 = v.x - m, d1 = v.y - m, d2 = v.z - m, d3 = v.w - m;
            float q = d0*d0 + d1*d1 + d2*d2 + d3*d3;
#pragma unroll
            for (int o = 16; o; o >>= 1) q += __shfl_xor_sync(0xffffffffu, q, o);
            float inv = rsqrtf(q * (1.f/128.f) + 1e-5f);
            v.x = d0*inv*gg.x + bb4.x;
            v.y = d1*inv*gg.y + bb4.y;
            v.z = d2*inv*gg.z + bb4.z;
            v.w = d3*inv*gg.w + bb4.w;
            Xr[lane] = v;

            float gs = v.x*wv4.x + v.y*wv4.y + v.z*wv4.z + v.w*wv4.w;
#pragma unroll
            for (int o = 16; o; o >>= 1) gs += __shfl_xor_sync(0xffffffffu, gs, o);
            if (lane == 0) {
                float vv = fmaxf(gs + bv0, 0.f);
                Vs[gr]  = vv;
                Vsm[gr] = vv * mask[gr];
            }

            uint32_t h0, l0, h1, l1;
            split2(v.x, v.y, h0, l0);
            split2(v.z, v.w, h1, l1);
            *(uint2*)(sm + P_XH + (uint32_t)(r * IROWB + lane * 8)) = make_uint2(h0, h1);
            *(uint2*)(sm + P_XL + (uint32_t)(r * IROWB + lane * 8)) = make_uint2(l0, l1);
        }
    }

    const int wr = w >> 1, wc = w & 1;
    const uint32_t a_row  = 16 * wr + (lane & 15);
    const uint32_t a_cadd = (lane & 16) ? 16 : 0;
    const uint32_t u_radd = (uint32_t)(lane & 15);
    const uint32_t u_cadd = (lane & 16) ? 16 : 0;
    const int r0 = 16 * wr + (lane >> 2), r1 = r0 + 8;

    for (int g = 0; g < 2; g++) {
        if (g == 1) {
            __syncthreads();   // all warps done reading Wq before overwrite
            for (int idx = tid; idx < 128 * 16; idx += 256) {
                int r = idx >> 4, c = idx & 15;
                uint32_t ro = (uint32_t)(r * IROWB + c * 16);
                cp16(sb + P_WH + ro, WuH + (size_t)r * 128 + c * 8);
                cp16(sb + P_WL + ro, WuL + (size_t)r * 128 + c * 8);
            }
            cp_commit();
        }
        cp_wait<0>();
        __syncthreads();

        float acc[8][4];
#pragma unroll
        for (int n = 0; n < 8; n++)
#pragma unroll
            for (int c = 0; c < 4; c++) acc[n][c] = 0.f;

#pragma unroll
        for (int kt = 0; kt < 8; kt++) {
            uint32_t aoff = a_row * IROWB + kt * 32 + a_cadd;
            uint32_t ah[4], al[4];
            ldsm_x4(ah, sb + P_XH + aoff);
            ldsm_x4(al, sb + P_XL + aoff);
#pragma unroll
            for (int npp = 0; npp < 2; npp++) {
                int np0 = 2 * npp, np1 = 2 * npp + 1;
                uint32_t b0off = (16 * kt + u_radd) * IROWB + wc * 128 + np0 * 32 + u_cadd;
                uint32_t b1off = (16 * kt + u_radd) * IROWB + wc * 128 + np1 * 32 + u_cadd;
                uint32_t bh0[4], bl0[4], bh1[4], bl1[4];
                ldsm_x4t(bh0, sb + P_WH + b0off);
                ldsm_x4t(bl0, sb + P_WL + b0off);
                ldsm_x4t(bh1, sb + P_WH + b1off);
                ldsm_x4t(bl1, sb + P_WL + b1off);
                mma_bf16(acc[2*np0],   ah, bh0[0], bh0[1]);
                mma_bf16(acc[2*np0+1], ah, bh0[2], bh0[3]);
                mma_bf16(acc[2*np1],   ah, bh1[0], bh1[1]);
                mma_bf16(acc[2*np1+1], ah, bh1[2], bh1[3]);
                mma_bf16(acc[2*np0],   ah, bl0[0], bl0[1]);
                mma_bf16(acc[2*np0+1], ah, bl0[2], bl0[3]);
                mma_bf16(acc[2*np1],   ah, bl1[0], bl1[1]);
                mma_bf16(acc[2*np1+1], ah, bl1[2], bl1[3]);
                mma_bf16(acc[2*np0],   al, bh0[0], bh0[1]);
                mma_bf16(acc[2*np0+1], al, bh0[2], bh0[3]);
                mma_bf16(acc[2*np1],   al, bh1[0], bh1[1]);
                mma_bf16(acc[2*np1+1], al, bh1[2], bh1[3]);
            }
        }

        const float* bias = g ? bu : bq;
        __nv_bfloat16* Oh = g ? Uh : Qh;
        __nv_bfloat16* Ol = g ? Ul : Ql;
#pragma unroll
        for (int n = 0; n < 8; n++) {
            int d = wc * 64 + 8 * n + 2 * (lane & 3);
            float2 bb = *(const float2*)(bias + d);
            float v00 = acc[n][0] + bb.x, v01 = acc[n][1] + bb.y;
            float v10 = acc[n][2] + bb.x, v11 = acc[n][3] + bb.y;
            if (g) {
                v00 = fmaxf(v00, 0.f); v01 = fmaxf(v01, 0.f);
                v10 = fmaxf(v10, 0.f); v11 = fmaxf(v11, 0.f);
            }
            uint32_t h, l;
            split2(v00, v01, h, l);
            *(uint32_t*)(Oh + (size_t)(row0 + r0) * 128 + d) = h;
            *(uint32_t*)(Ol + (size_t)(row0 + r0) * 128 + d) = l;
            split2(v10, v11, h, l);
            *(uint32_t*)(Oh + (size_t)(row0 + r1) * 128 + d) = h;
            *(uint32_t*)(Ol + (size_t)(row0 + r1) * 128 + d) = l;
        }
    }
}

// =====================================================================
// embed (mma): unchanged (64-row CTAs, preconverted W, 2 CTAs/SM)
// =====================================================================
__global__ __launch_bounds__(256, 2) void embed_mma_kernel(
    const float* __restrict__ A1, const float* __restrict__ A2,
    const __nv_bfloat16* __restrict__ WHb, const __nv_bfloat16* __restrict__ WLb,
    const float* __restrict__ b1, const float* __restrict__ b2,
    float* __restrict__ out1, float* __restrict__ out2) {
    extern __shared__ __align__(16) char sm[];
    const int tid = threadIdx.x;
    const int w   = tid >> 5, lane = tid & 31;
    const int row0 = blockIdx.x * 64;
    const int z = blockIdx.y;
    const uint32_t sb = smem_u32(sm);

    const float* A = z ? A2 : A1;
    const __nv_bfloat16* WH = WHb + z * 16384;
    const __nv_bfloat16* WL = WLb + z * 16384;
    const float* bias = z ? b2 : b1;
    float* out = z ? out2 : out1;

    for (int idx = tid; idx < 128 * 16; idx += 256) {
        int r = idx >> 4, c = idx & 15;
        uint32_t ro = (uint32_t)(r * IROWB + c * 16);
        cp16(sb + P_WH + ro, WH + (size_t)r * 128 + c * 8);
        cp16(sb + P_WL + ro, WL + (size_t)r * 128 + c * 8);
    }
    cp_commit();
    for (int idx = tid; idx < 64 * 32; idx += 256) {
        int r = idx >> 5, cq = idx & 31;
        uint32_t off = (uint32_t)(r * IROWB + cq * 8);
        uint32_t h0, l0, h1, l1;
        float4 av = *(const float4*)(A + (size_t)(row0 + r) * 128 + cq * 4);
        split2(av.x, av.y, h0, l0);
        split2(av.z, av.w, h1, l1);
        *(uint2*)(sm + P_XH + off) = make_uint2(h0, h1);
        *(uint2*)(sm + P_XL + off) = make_uint2(l0, l1);
    }
    cp_wait<0>();
    __syncthreads();

    const int wr = w >> 1, wc = w & 1;
    const uint32_t a_row  = 16 * wr + (lane & 15);
    const uint32_t a_cadd = (lane & 16) ? 16 : 0;
    const uint32_t u_radd = (uint32_t)(lane & 15);
    const uint32_t u_cadd = (lane & 16) ? 16 : 0;
    const int r0 = 16 * wr + (lane >> 2), r1 = r0 + 8;

    float acc[8][4];
#pragma unroll
    for (int n = 0; n < 8; n++)
#pragma unroll
        for (int c = 0; c < 4; c++) acc[n][c] = 0.f;

#pragma unroll
    for (int kt = 0; kt < 8; kt++) {
        uint32_t aoff = a_row * IROWB + kt * 32 + a_cadd;
        uint32_t ah[4], al[4];
        ldsm_x4(ah, sb + P_XH + aoff);
        ldsm_x4(al, sb + P_XL + aoff);
#pragma unroll
        for (int npp = 0; npp < 2; npp++) {
            int np0 = 2 * npp, np1 = 2 * npp + 1;
            uint32_t b0off = (16 * kt + u_radd) * IROWB + wc * 128 + np0 * 32 + u_cadd;
            uint32_t b1off = (16 * kt + u_radd) * IROWB + wc * 128 + np1 * 32 + u_cadd;
            uint32_t bh0[4], bl0[4], bh1[4], bl1[4];
            ldsm_x4t(bh0, sb + P_WH + b0off);
            ldsm_x4t(bl0, sb + P_WL + b0off);
            ldsm_x4t(bh1, sb + P_WH + b1off);
            ldsm_x4t(bl1, sb + P_WL + b1off);
            mma_bf16(acc[2*np0],   ah, bh0[0], bh0[1]);
            mma_bf16(acc[2*np0+1], ah, bh0[2], bh0[3]);
            mma_bf16(acc[2*np1],   ah, bh1[0], bh1[1]);
            mma_bf16(acc[2*np1+1], ah, bh1[2], bh1[3]);
            mma_bf16(acc[2*np0],   ah, bl0[0], bl0[1]);
            mma_bf16(acc[2*np0+1], ah, bl0[2], bl0[3]);
            mma_bf16(acc[2*np1],   ah, bl1[0], bl1[1]);
            mma_bf16(acc[2*np1+1], ah, bl1[2], bl1[3]);
            mma_bf16(acc[2*np0],   al, bh0[0], bh0[1]);
            mma_bf16(acc[2*np0+1], al, bh0[2], bh0[3]);
            mma_bf16(acc[2*np1],   al, bh1[0], bh1[1]);
            mma_bf16(acc[2*np1+1], al, bh1[2], bh1[3]);
        }
    }

#pragma unroll
    for (int n = 0; n < 8; n++) {
        int d = wc * 64 + 8 * n + 2 * (lane & 3);
        float2 bb = *(const float2*)(bias + d);
        float2 o0, o1;
        o0.x = fmaxf(acc[n][0] + bb.x, 0.f);
        o0.y = fmaxf(acc[n][1] + bb.y, 0.f);
        o1.x = fmaxf(acc[n][2] + bb.x, 0.f);
        o1.y = fmaxf(acc[n][3] + bb.y, 0.f);
        *(float2*)(out + (size_t)(row0 + r0) * 128 + d) = o0;
        *(float2*)(out + (size_t)(row0 + r1) * 128 + d) = o1;
    }
}

__device__ __forceinline__ float blk_reduce(float v, float* red, bool ismax) {
#pragma unroll
    for (int o = 16; o; o >>= 1) {
        float t = __shfl_xor_sync(0xffffffffu, v, o);
        v = ismax ? fmaxf(v, t) : v + t;
    }
    if ((threadIdx.x & 31) == 0) red[threadIdx.x >> 5] = v;
    __syncthreads();
    float r = red[0];
#pragma unroll
    for (int i = 1; i < (int)(blockDim.x >> 5); i++) r = ismax ? fmaxf(r, red[i]) : r + red[i];
    __syncthreads();
    return r;
}

// ---------------- pooling: one CTA per (batch, sequence) ----------------
__global__ __launch_bounds__(256) void pool_kernel(
    const float* __restrict__ Xg, const float* __restrict__ Yg,
    float* __restrict__ pooled) {
    __shared__ float w[1024];
    __shared__ float red[8];
    __shared__ float pp[256];
    const int tid = threadIdx.x;
    const int b   = blockIdx.x;
    const int s   = blockIdx.y;

    const float* S = (s ? Yg : Xg) + (size_t)b * SEQL * 128;
    for (int l = tid; l < SEQL; l += 256) {
        const float4* row = (const float4*)(S + (size_t)l*128);
        float acc = 0.f;
#pragma unroll
        for (int c = 0; c < 32; c++) {
            float4 v = row[c];
            acc += v.x*v.x + v.y*v.y + v.z*v.z + v.w*v.w;
        }
        w[l] = sqrtf(acc);
    }
    __syncthreads();
    float lm = -1e30f;
    for (int l = tid; l < SEQL; l += 256) lm = fmaxf(lm, w[l]);
    float mx = blk_reduce(lm, red, true);
    float ls = 0.f;
    for (int l = tid; l < SEQL; l += 256) { float e = expf(w[l] - mx); w[l] = e; ls += e; }
    float tot = blk_reduce(ls, red, false);
    float inv = 1.f / tot;

    int d = tid & 127, halfi = tid >> 7;
    float p = 0.f;
    for (int l = halfi; l < SEQL; l += 2) p += S[(size_t)l*128 + d] * w[l];
    pp[halfi*128 + d] = p;
    __syncthreads();
    if (tid < 128)
        pooled[(s * 16 + b) * 128 + tid] = (pp[tid] + pp[128 + tid]) * inv;
}

// ---------------- head: 16 tiny CTAs ----------------
__global__ __launch_bounds__(128) void head_kernel(
    const float* __restrict__ pooled,
    const float* __restrict__ fc_w, const float* __restrict__ fc_b,
    const float* __restrict__ out_w, const float* __restrict__ out_b,
    float* __restrict__ out) {
    __shared__ float xp[128];
    __shared__ float yp[128];
    __shared__ float red[4];
    const int tid = threadIdx.x;
    const int b   = blockIdx.x;

    xp[tid] = pooled[b * 128 + tid];
    yp[tid] = pooled[(16 + b) * 128 + tid];
    __syncthreads();

    float h = fc_b[tid];
    for (int k2 = 0; k2 < 128; k2++) h += xp[k2] * fc_w[k2*128 + tid];
    for (int k2 = 0; k2 < 128; k2++) h += yp[k2] * fc_w[(128 + k2)*128 + tid];
    h = fmaxf(h, 0.f) * out_w[tid];
    float tot = blk_reduce(h, red, false);
    if (tid == 0) out[b] = 1.f / (1.f + expf(-(tot + out_b[0])));
}

// ---------------- launch ----------------
extern "C" void kernel_launch(void* const* d_in, const int* in_sizes, int n_in,
                              void* d_out, int out_size) {
    (void)in_sizes; (void)n_in; (void)out_size;
    const float* seq1  = (const float*)d_in[0];
    const float* seq2  = (const float*)d_in[1];
    const float* mask1 = (const float*)d_in[2];
    const float* mask2 = (const float*)d_in[3];
    const float* l1_w  = (const float*)d_in[4];
    const float* l1_b  = (const float*)d_in[5];
    const float* l2_w  = (const float*)d_in[6];
    const float* l2_b  = (const float*)d_in[7];
    const float* ln1_g = (const float*)d_in[8];
    const float* ln1_b = (const float*)d_in[9];
    const float* ln2_g = (const float*)d_in[10];
    const float* ln2_b = (const float*)d_in[11];
    const float* wq_w  = (const float*)d_in[12];
    const float* wq_b  = (const float*)d_in[13];
    const float* wk_w  = (const float*)d_in[14];
    const float* wk_b  = (const float*)d_in[15];
    const float* wvx_w = (const float*)d_in[16];
    const float* wvx_b = (const float*)d_in[17];
    const float* wvy_w = (const float*)d_in[18];
    const float* wvy_b = (const float*)d_in[19];
    const float* wx_w  = (const float*)d_in[20];
    const float* wx_b  = (const float*)d_in[21];
    const float* wy_w  = (const float*)d_in[22];
    const float* wy_b  = (const float*)d_in[23];
    const float* fc_w  = (const float*)d_in[24];
    const float* fc_b  = (const float*)d_in[25];
    const float* out_w = (const float*)d_in[26];
    const float* out_b = (const float*)d_in[27];

    float *x, *y, *vx, *vy, *vxm, *vym, *pool;
    __nv_bfloat16 *qh, *ql, *kh, *kl, *xuh, *xul, *yuh, *yul, *wbh, *wbl;
    cudaGetSymbolAddress((void**)&x,   g_x);
    cudaGetSymbolAddress((void**)&y,   g_y);
    cudaGetSymbolAddress((void**)&qh,  g_qh);
    cudaGetSymbolAddress((void**)&ql,  g_ql);
    cudaGetSymbolAddress((void**)&kh,  g_kh);
    cudaGetSymbolAddress((void**)&kl,  g_kl);
    cudaGetSymbolAddress((void**)&xuh, g_xuh);
    cudaGetSymbolAddress((void**)&xul, g_xul);
    cudaGetSymbolAddress((void**)&yuh, g_yuh);
    cudaGetSymbolAddress((void**)&yul, g_yul);
    cudaGetSymbolAddress((void**)&vx,  g_vx);
    cudaGetSymbolAddress((void**)&vy,  g_vy);
    cudaGetSymbolAddress((void**)&vxm, g_vxm);
    cudaGetSymbolAddress((void**)&vym, g_vym);
    cudaGetSymbolAddress((void**)&pool, g_pool);
    cudaGetSymbolAddress((void**)&wbh, g_wbh);
    cudaGetSymbolAddress((void**)&wbl, g_wbl);

    cudaFuncSetAttribute(embed_mma_kernel,    cudaFuncAttributeMaxDynamicSharedMemorySize, P_SMEM);
    cudaFuncSetAttribute(proj_mma_kernel,     cudaFuncAttributeMaxDynamicSharedMemorySize, P_SMEM);
    cudaFuncSetAttribute(interact_mma_kernel, cudaFuncAttributeMaxDynamicSharedMemorySize, I_SMEM);

    prep_w_kernel<<<dim3(32, 14), 256>>>(l1_w, l2_w, wq_w, wx_w, wk_w, wy_w, wbh, wbl);

    embed_mma_kernel<<<dim3(256, 2), 256, P_SMEM>>>(seq1, seq2, wbh, wbl,
                                                    l1_b, l2_b, x, y);

    for (int i = 0; i < 3; i++) {
        int base = 2 + i * 4;
        proj_mma_kernel<<<dim3(256, 2), 256, P_SMEM>>>(
            x, y,
            ln1_g + i*128, ln1_b + i*128, ln2_g + i*128, ln2_b + i*128,
            wbh + (base+0)*16384, wbl + (base+0)*16384, wq_b + i*128,
            wbh + (base+1)*16384, wbl + (base+1)*16384, wx_b + i*128,
            wvx_w + i*128, wvx_b + i,
            wbh + (base+2)*16384, wbl + (base+2)*16384, wk_b + i*128,
            wbh + (base+3)*16384, wbl + (base+3)*16384, wy_b + i*128,
            wvy_w + i*128, wvy_b + i,
            mask1, mask2,
            qh, ql, xuh, xul, kh, kl, yuh, yul,
            vx, vxm, vy, vym);
        interact_mma_kernel<<<dim3(16, 16, 2), 128, I_SMEM>>>(
            qh, ql, kh, kl, xuh, xul, yuh, yul, vxm, vy, vym, vx, x, y);
    }
    pool_kernel<<<dim3(16, 2), 256>>>(x, y, pool);
    head_kernel<<<16, 128>>>(pool, fc_w, fc_b, out_w, out_b, (float*)d_out);
}

// round 16
// speedup vs baseline: 1.2633x; 1.0997x over previous
#include <cuda_runtime.h>
#include <cuda_bf16.h>
#include <cstdint>
#include <math.h>

#define NROWS 16384        // B * L = 16 * 1024
#define SEQL  1024
#define SCALE_INV 0.08838834764831845f   // 1/sqrt(128)

// ---------------- persistent scratch ----------------
__device__ float g_x [NROWS*128];
__device__ float g_y [NROWS*128];
__device__ __nv_bfloat16 g_qh [NROWS*128];
__device__ __nv_bfloat16 g_ql [NROWS*128];
__device__ __nv_bfloat16 g_kh [NROWS*128];
__device__ __nv_bfloat16 g_kl [NROWS*128];
__device__ __nv_bfloat16 g_xuh[NROWS*128];
__device__ __nv_bfloat16 g_xul[NROWS*128];
__device__ __nv_bfloat16 g_yuh[NROWS*128];
__device__ __nv_bfloat16 g_yul[NROWS*128];
__device__ float g_vx [NROWS];
__device__ float g_vy [NROWS];
__device__ float g_vxm[NROWS];
__device__ float g_vym[NROWS];
__device__ float g_pool[2*16*128];
// preconverted weights: 14 matrices of 128x128
__device__ __align__(16) __nv_bfloat16 g_wbh[14*16384];
__device__ __align__(16) __nv_bfloat16 g_wbl[14*16384];

__device__ __forceinline__ float sigmoidf_fast(float x) {
    return __fdividef(1.f, 1.f + __expf(-x));
}

__device__ __forceinline__ uint32_t smem_u32(const void* p) {
    uint32_t a;
    asm("{ .reg .u64 t; cvta.to.shared.u64 t, %1; cvt.u32.u64 %0, t; }" : "=r"(a) : "l"(p));
    return a;
}

__device__ __forceinline__ uint32_t packbf(__nv_bfloat16 a, __nv_bfloat16 b) {
    __nv_bfloat162 t(a, b);
    return *reinterpret_cast<uint32_t*>(&t);
}

__device__ __forceinline__ void split2(float a, float b, uint32_t& hi, uint32_t& lo) {
    __nv_bfloat16 h0 = __float2bfloat16_rn(a), h1 = __float2bfloat16_rn(b);
    hi = packbf(h0, h1);
    lo = packbf(__float2bfloat16_rn(a - __bfloat162float(h0)),
                __float2bfloat16_rn(b - __bfloat162float(h1)));
}

__device__ __forceinline__ void ldsm_x4(uint32_t r[4], uint32_t addr) {
    asm volatile("ldmatrix.sync.aligned.m8n8.x4.shared.b16 {%0,%1,%2,%3}, [%4];"
                 : "=r"(r[0]), "=r"(r[1]), "=r"(r[2]), "=r"(r[3]) : "r"(addr));
}
__device__ __forceinline__ void ldsm_x4t(uint32_t r[4], uint32_t addr) {
    asm volatile("ldmatrix.sync.aligned.m8n8.x4.trans.shared.b16 {%0,%1,%2,%3}, [%4];"
                 : "=r"(r[0]), "=r"(r[1]), "=r"(r[2]), "=r"(r[3]) : "r"(addr));
}
__device__ __forceinline__ void mma_bf16(float c[4], const uint32_t a[4],
                                         uint32_t b0, uint32_t b1) {
    asm volatile(
        "mma.sync.aligned.m16n8k16.row.col.f32.bf16.bf16.f32 "
        "{%0,%1,%2,%3}, {%4,%5,%6,%7}, {%8,%9}, {%0,%1,%2,%3};"
        : "+f"(c[0]), "+f"(c[1]), "+f"(c[2]), "+f"(c[3])
        : "r"(a[0]), "r"(a[1]), "r"(a[2]), "r"(a[3]), "r"(b0), "r"(b1));
}

__device__ __forceinline__ void cp16(uint32_t saddr, const void* g) {
    asm volatile("cp.async.cg.shared.global [%0], [%1], 16;" :: "r"(saddr), "l"(g));
}
__device__ __forceinline__ void cp_commit() {
    asm volatile("cp.async.commit_group;" ::: "memory");
}
template<int N>
__device__ __forceinline__ void cp_wait() {
    asm volatile("cp.async.wait_group %0;" :: "n"(N) : "memory");
}

// ---- smem geometry ----
#define IROWB 272
#define QTILE (128 * IROWB)      // 34816
#define STILE (64 * IROWB)       // 17408
#define JTILE (32 * IROWB)       // 8704

// interact smem: 128-thr CTA, 64 i-rows, 32-row j-tiles; K staged hi-only.
#define O_QH  0
#define O_QL  STILE
#define O_ST  (2 * STILE)        // 34816
#define S_KH  0
#define S_UH  JTILE
#define S_UL  (2 * JTILE)
#define S_BS  (3 * JTILE)        // 32 floats
#define STAGE (3 * JTILE + 256)  // 26368
#define O_AS  (O_ST + 2 * STAGE) // 87552
#define I_SMEM (O_AS + 256)      // 87808  (2 CTAs/SM)

// proj / embed smem
#define P_XH  0
#define P_XL  STILE
#define P_WH  (2 * STILE)
#define P_WL  (P_WH + QTILE)
#define P_SMEM (P_WL + QTILE)    // 104448

// =====================================================================
// prep: convert 14 weight matrices fp32 -> bf16 hi/lo in gmem (once)
// =====================================================================
__global__ __launch_bounds__(256) void prep_w_kernel(
    const float* __restrict__ l1_w, const float* __restrict__ l2_w,
    const float* __restrict__ wq_w, const float* __restrict__ wx_w,
    const float* __restrict__ wk_w, const float* __restrict__ wy_w,
    __nv_bfloat16* __restrict__ WH, __nv_bfloat16* __restrict__ WL) {
    int m = blockIdx.y;
    const float* src;
    if (m == 0) src = l1_w;
    else if (m == 1) src = l2_w;
    else {
        int i = (m - 2) >> 2, r = (m - 2) & 3;
        src = (r == 0 ? wq_w : r == 1 ? wx_w : r == 2 ? wk_w : wy_w) + i * 16384;
    }
    int idx = blockIdx.x * 256 + threadIdx.x;
    float2 v = *(const float2*)(src + 2 * idx);
    uint32_t h, l;
    split2(v.x, v.y, h, l);
    *(uint32_t*)(WH + m * 16384 + 2 * idx) = h;
    *(uint32_t*)(WL + m * 16384 + 2 * idx) = l;
}

// =====================================================================
// interact: R15 structure; GEMM1 = (Ah+Al) x Kh (K-lo dropped -- probe).
// GEMM2 stays full 3-term. 128 thr / 4 warps, 64 i-rows, 32-row j-tiles.
// =====================================================================
__global__ __launch_bounds__(128, 2) void interact_mma_kernel(
    const __nv_bfloat16* __restrict__ qh, const __nv_bfloat16* __restrict__ ql,
    const __nv_bfloat16* __restrict__ kh, const __nv_bfloat16* __restrict__ kl,
    const __nv_bfloat16* __restrict__ xuh, const __nv_bfloat16* __restrict__ xul,
    const __nv_bfloat16* __restrict__ yuh, const __nv_bfloat16* __restrict__ yul,
    const float* __restrict__ vxm, const float* __restrict__ vy,
    const float* __restrict__ vym, const float* __restrict__ vx,
    float* __restrict__ xO, float* __restrict__ yO) {
    extern __shared__ __align__(16) char sm[];
    const int tid  = threadIdx.x;
    const int w    = tid >> 5, lane = tid & 31;
    const int b    = blockIdx.y;
    const int i0   = blockIdx.x * 64;
    const int z    = blockIdx.z;
    const uint32_t sb = smem_u32(sm);
    float* aSs = (float*)(sm + O_AS);

    const __nv_bfloat16* Ah = z ? kh  : qh;
    const __nv_bfloat16* Al = z ? kl  : ql;
    const __nv_bfloat16* Kh = z ? qh  : kh;
    const __nv_bfloat16* Uh = z ? xuh : yuh;
    const __nv_bfloat16* Ul = z ? xul : yul;
    const float* aS = z ? vym : vxm;
    const float* bS = z ? vx  : vy;
    float* Out      = z ? yO  : xO;

    const size_t rowbase = (size_t)(b * SEQL + i0) * 128;

    for (int i = tid; i < 64 * 16; i += 128) {
        int r = i >> 4, c = i & 15;
        uint32_t ro = (uint32_t)(r * IROWB + c * 16);
        size_t go = rowbase + (size_t)r * 128 + c * 8;
        cp16(sb + O_QH + ro, Ah + go);
        cp16(sb + O_QL + ro, Al + go);
    }
    if (tid < 16) cp16(sb + O_AS + tid * 16, aS + b * SEQL + i0 + tid * 4);

#define ISSUE_STAGE(JT, BUF) do { \
        const size_t jb = (size_t)(b * SEQL + (JT) * 32) * 128; \
        uint32_t st = sb + O_ST + (BUF) * STAGE; \
        for (int i = tid; i < 32 * 16; i += 128) { \
            int r = i >> 4, c = i & 15; \
            uint32_t ro = (uint32_t)(r * IROWB + c * 16); \
            size_t go = jb + (size_t)r * 128 + c * 8; \
            cp16(st + S_KH + ro, Kh + go); \
            cp16(st + S_UH + ro, Uh + go); \
            cp16(st + S_UL + ro, Ul + go); \
        } \
        if (tid < 8) cp16(st + S_BS + tid * 16, bS + b * SEQL + (JT) * 32 + tid * 4); \
    } while (0)

    ISSUE_STAGE(0, 0);
    cp_commit();

    float oacc[16][4];
#pragma unroll
    for (int n = 0; n < 16; n++)
#pragma unroll
        for (int c = 0; c < 4; c++) oacc[n][c] = 0.f;

    const uint32_t a_row  = 16 * w + (lane & 15);
    const uint32_t a_cadd = (lane & 16) ? 16 : 0;
    const uint32_t b_rsub = (uint32_t)(((lane & 16) ? 8 : 0) + (lane & 7));
    const uint32_t b_cadd = (lane & 8) ? 16 : 0;
    const uint32_t u_radd = (uint32_t)(lane & 15);
    const uint32_t u_cadd = (lane & 16) ? 16 : 0;

    uint32_t ahr[8][4], alr[8][4];

    for (int jt = 0; jt < 32; jt++) {
        if (jt + 1 < 32) {
            ISSUE_STAGE(jt + 1, (jt + 1) & 1);
            cp_commit();
            cp_wait<1>();
        } else {
            cp_wait<0>();
        }
        __syncthreads();

        if (jt == 0) {
#pragma unroll
            for (int kt = 0; kt < 8; kt++) {
                uint32_t aoff = a_row * IROWB + kt * 32 + a_cadd;
                ldsm_x4(ahr[kt], sb + O_QH + aoff);
                ldsm_x4(alr[kt], sb + O_QL + aoff);
            }
        }

        const uint32_t st = sb + O_ST + (jt & 1) * STAGE;
        const float* bSs = (const float*)(sm + O_ST + (jt & 1) * STAGE + S_BS);

        // ---- GEMM1: S[16 x 32] = (Ah+Al) @ Kh^T (K-lo dropped) ----
        float sacc[4][4];
#pragma unroll
        for (int n = 0; n < 4; n++)
#pragma unroll
            for (int c = 0; c < 4; c++) sacc[n][c] = 0.f;

#pragma unroll
        for (int kt = 0; kt < 8; kt++) {
            uint32_t b0off = b_rsub * IROWB + kt * 32 + b_cadd;
            uint32_t b1off = (16 + b_rsub) * IROWB + kt * 32 + b_cadd;
            uint32_t bh0[4], bh1[4];
            ldsm_x4(bh0, st + S_KH + b0off);
            ldsm_x4(bh1, st + S_KH + b1off);
            mma_bf16(sacc[0], ahr[kt], bh0[0], bh0[1]);
            mma_bf16(sacc[1], ahr[kt], bh0[2], bh0[3]);
            mma_bf16(sacc[2], ahr[kt], bh1[0], bh1[1]);
            mma_bf16(sacc[3], ahr[kt], bh1[2], bh1[3]);
            mma_bf16(sacc[0], alr[kt], bh0[0], bh0[1]);
            mma_bf16(sacc[1], alr[kt], bh0[2], bh0[3]);
            mma_bf16(sacc[2], alr[kt], bh1[0], bh1[1]);
            mma_bf16(sacc[3], alr[kt], bh1[2], bh1[3]);
        }

        uint32_t ph[4][2], pl[4][2];
#pragma unroll
        for (int n = 0; n < 4; n++) {
            int j0 = 8 * n + 2 * (lane & 3);
            float2 bv = *(const float2*)(bSs + j0);
            float p00 = sigmoidf_fast(sacc[n][0] * SCALE_INV) * bv.x;
            float p01 = sigmoidf_fast(sacc[n][1] * SCALE_INV) * bv.y;
            float p10 = sigmoidf_fast(sacc[n][2] * SCALE_INV) * bv.x;
            float p11 = sigmoidf_fast(sacc[n][3] * SCALE_INV) * bv.y;
            split2(p00, p01, ph[n][0], pl[n][0]);
            split2(p10, p11, ph[n][1], pl[n][1]);
        }

        // ---- GEMM2: O += (Ph+Pl) @ (Uh+Ul)  (full 3-term) ----
#pragma unroll
        for (int kt = 0; kt < 2; kt++) {
            uint32_t ah[4] = { ph[2*kt][0], ph[2*kt][1], ph[2*kt+1][0], ph[2*kt+1][1] };
            uint32_t al[4] = { pl[2*kt][0], pl[2*kt][1], pl[2*kt+1][0], pl[2*kt+1][1] };
#pragma unroll
            for (int npp = 0; npp < 4; npp++) {
                int np0 = 2 * npp, np1 = 2 * npp + 1;
                uint32_t u0off = (16 * kt + u_radd) * IROWB + np0 * 32 + u_cadd;
                uint32_t u1off = (16 * kt + u_radd) * IROWB + np1 * 32 + u_cadd;
                uint32_t uh0[4], ul0[4], uh1[4], ul1[4];
                ldsm_x4t(uh0, st + S_UH + u0off);
                ldsm_x4t(ul0, st + S_UL + u0off);
                ldsm_x4t(uh1, st + S_UH + u1off);
                ldsm_x4t(ul1, st + S_UL + u1off);
                mma_bf16(oacc[2*np0],   ah, uh0[0], uh0[1]);
                mma_bf16(oacc[2*np0+1], ah, uh0[2], uh0[3]);
                mma_bf16(oacc[2*np1],   ah, uh1[0], uh1[1]);
                mma_bf16(oacc[2*np1+1], ah, uh1[2], uh1[3]);
                mma_bf16(oacc[2*np0],   ah, ul0[0], ul0[1]);
                mma_bf16(oacc[2*np0+1], ah, ul0[2], ul0[3]);
                mma_bf16(oacc[2*np1],   ah, ul1[0], ul1[1]);
                mma_bf16(oacc[2*np1+1], ah, ul1[2], ul1[3]);
                mma_bf16(oacc[2*np0],   al, uh0[0], uh0[1]);
                mma_bf16(oacc[2*np0+1], al, uh0[2], uh0[3]);
                mma_bf16(oacc[2*np1],   al, uh1[0], uh1[1]);
                mma_bf16(oacc[2*np1+1], al, uh1[2], uh1[3]);
            }
        }
        __syncthreads();
    }
#undef ISSUE_STAGE

    {
        int r0 = 16 * w + (lane >> 2), r1 = r0 + 8;
        float av0 = aSs[r0], av1 = aSs[r1];
        float* Ob = Out + rowbase;
#pragma unroll
        for (int n = 0; n < 16; n++) {
            int d = 8 * n + 2 * (lane & 3);
            float2 o0 = *(float2*)(Ob + (size_t)r0 * 128 + d);
            o0.x += av0 * oacc[n][0];
            o0.y += av0 * oacc[n][1];
            *(float2*)(Ob + (size_t)r0 * 128 + d) = o0;
            float2 o1 = *(float2*)(Ob + (size_t)r1 * 128 + d);
            o1.x += av1 * oacc[n][2];
            o1.y += av1 * oacc[n][3];
            *(float2*)(Ob + (size_t)r1 * 128 + d) = o1;
        }
    }
}

// =====================================================================
// proj (mma) with fused LN; Wq prefetched before the LN phase. R15 verbatim.
// =====================================================================
__global__ __launch_bounds__(256, 2) void proj_mma_kernel(
    float* __restrict__ X1, float* __restrict__ X2,
    const float* __restrict__ lng1, const float* __restrict__ lnb1,
    const float* __restrict__ lng2, const float* __restrict__ lnb2,
    const __nv_bfloat16* __restrict__ WqH1, const __nv_bfloat16* __restrict__ WqL1,
    const float* __restrict__ bq1,
    const __nv_bfloat16* __restrict__ WuH1, const __nv_bfloat16* __restrict__ WuL1,
    const float* __restrict__ bu1,
    const float* __restrict__ wv1, const float* __restrict__ bv1,
    const __nv_bfloat16* __restrict__ WqH2, const __nv_bfloat16* __restrict__ WqL2,
    const float* __restrict__ bq2,
    const __nv_bfloat16* __restrict__ WuH2, const __nv_bfloat16* __restrict__ WuL2,
    const float* __restrict__ bu2,
    const float* __restrict__ wv2, const float* __restrict__ bv2,
    const float* __restrict__ mask1, const float* __restrict__ mask2,
    __nv_bfloat16* __restrict__ qh, __nv_bfloat16* __restrict__ ql,
    __nv_bfloat16* __restrict__ xuh, __nv_bfloat16* __restrict__ xul,
    __nv_bfloat16* __restrict__ kh, __nv_bfloat16* __restrict__ kl,
    __nv_bfloat16* __restrict__ yuh, __nv_bfloat16* __restrict__ yul,
    float* __restrict__ vx, float* __restrict__ vxm,
    float* __restrict__ vy, float* __restrict__ vym) {
    extern __shared__ __align__(16) char sm[];
    const int tid = threadIdx.x;
    const int w   = tid >> 5, lane = tid & 31;
    const int row0 = blockIdx.x * 64;
    const int z = blockIdx.y;
    const uint32_t sb = smem_u32(sm);

    float* X = z ? X2 : X1;
    const float* lng = z ? lng2 : lng1;
    const float* lnb = z ? lnb2 : lnb1;
    const __nv_bfloat16* WqH = z ? WqH2 : WqH1;
    const __nv_bfloat16* WqL = z ? WqL2 : WqL1;
    const __nv_bfloat16* WuH = z ? WuH2 : WuH1;
    const __nv_bfloat16* WuL = z ? WuL2 : WuL1;
    const float* bq = z ? bq2 : bq1;
    const float* bu = z ? bu2 : bu1;
    const float* wv = z ? wv2 : wv1;
    const float* bv = z ? bv2 : bv1;
    const float* mask = z ? mask2 : mask1;
    __nv_bfloat16* Qh = z ? kh : qh;
    __nv_bfloat16* Ql = z ? kl : ql;
    __nv_bfloat16* Uh = z ? yuh : xuh;
    __nv_bfloat16* Ul = z ? yul : xul;
    float* Vs  = z ? vy : vx;
    float* Vsm = z ? vym : vxm;

    for (int idx = tid; idx < 128 * 16; idx += 256) {
        int r = idx >> 4, c = idx & 15;
        uint32_t ro = (uint32_t)(r * IROWB + c * 16);
        cp16(sb + P_WH + ro, WqH + (size_t)r * 128 + c * 8);
        cp16(sb + P_WL + ro, WqL + (size_t)r * 128 + c * 8);
    }
    cp_commit();

    {
        float4 gg  = ((const float4*)lng)[lane];
        float4 bb4 = ((const float4*)lnb)[lane];
        float4 wv4 = ((const float4*)wv)[lane];
        float bv0 = bv[0];
        for (int rr = 0; rr < 8; rr++) {
            int r  = 8 * w + rr;
            int gr = row0 + r;
            float4* Xr = (float4*)(X + (size_t)gr * 128);
            float4 v = Xr[lane];
            float s = v.x + v.y + v.z + v.w;
#pragma unroll
            for (int o = 16; o; o >>= 1) s += __shfl_xor_sync(0xffffffffu, s, o);
            float m = s * (1.f/128.f);
            float d0 = v.x - m, d1 = v.y - m, d2 = v.z - m, d3 = v.w - m;
            float q = d0*d0 + d1*d1 + d2*d2 + d3*d3;
#pragma unroll
            for (int o = 16; o; o >>= 1) q += __shfl_xor_sync(0xffffffffu, q, o);
            float inv = rsqrtf(q * (1.f/128.f) + 1e-5f);
            v.x = d0*inv*gg.x + bb4.x;
            v.y = d1*inv*gg.y + bb4.y;
            v.z = d2*inv*gg.z + bb4.z;
            v.w = d3*inv*gg.w + bb4.w;
            Xr[lane] = v;

            float gs = v.x*wv4.x + v.y*wv4.y + v.z*wv4.z + v.w*wv4.w;
#pragma unroll
            for (int o = 16; o; o >>= 1) gs += __shfl_xor_sync(0xffffffffu, gs, o);
            if (lane == 0) {
                float vv = fmaxf(gs + bv0, 0.f);
                Vs[gr]  = vv;
                Vsm[gr] = vv * mask[gr];
            }

            uint32_t h0, l0, h1, l1;
            split2(v.x, v.y, h0, l0);
            split2(v.z, v.w, h1, l1);
            *(uint2*)(sm + P_XH + (uint32_t)(r * IROWB + lane * 8)) = make_uint2(h0, h1);
            *(uint2*)(sm + P_XL + (uint32_t)(r * IROWB + lane * 8)) = make_uint2(l0, l1);
        }
    }

    const int wr = w >> 1, wc = w & 1;
    const uint32_t a_row  = 16 * wr + (lane & 15);
    const uint32_t a_cadd = (lane & 16) ? 16 : 0;
    const uint32_t u_radd = (uint32_t)(lane & 15);
    const uint32_t u_cadd = (lane & 16) ? 16 : 0;
    const int r0 = 16 * wr + (lane >> 2), r1 = r0 + 8;

    for (int g = 0; g < 2; g++) {
        if (g == 1) {
            __syncthreads();
            for (int idx = tid; idx < 128 * 16; idx += 256) {
                int r = idx >> 4, c = idx & 15;
                uint32_t ro = (uint32_t)(r * IROWB + c * 16);
                cp16(sb + P_WH + ro, WuH + (size_t)r * 128 + c * 8);
                cp16(sb + P_WL + ro, WuL + (size_t)r * 128 + c * 8);
            }
            cp_commit();
        }
        cp_wait<0>();
        __syncthreads();

        float acc[8][4];
#pragma unroll
        for (int n = 0; n < 8; n++)
#pragma unroll
            for (int c = 0; c < 4; c++) acc[n][c] = 0.f;

#pragma unroll
        for (int kt = 0; kt < 8; kt++) {
            uint32_t aoff = a_row * IROWB + kt * 32 + a_cadd;
            uint32_t ah[4], al[4];
            ldsm_x4(ah, sb + P_XH + aoff);
            ldsm_x4(al, sb + P_XL + aoff);
#pragma unroll
            for (int npp = 0; npp < 2; npp++) {
                int np0 = 2 * npp, np1 = 2 * npp + 1;
                uint32_t b0off = (16 * kt + u_radd) * IROWB + wc * 128 + np0 * 32 + u_cadd;
                uint32_t b1off = (16 * kt + u_radd) * IROWB + wc * 128 + np1 * 32 + u_cadd;
                uint32_t bh0[4], bl0[4], bh1[4], bl1[4];
                ldsm_x4t(bh0, sb + P_WH + b0off);
                ldsm_x4t(bl0, sb + P_WL + b0off);
                ldsm_x4t(bh1, sb + P_WH + b1off);
                ldsm_x4t(bl1, sb + P_WL + b1off);
                mma_bf16(acc[2*np0],   ah, bh0[0], bh0[1]);
                mma_bf16(acc[2*np0+1], ah, bh0[2], bh0[3]);
                mma_bf16(acc[2*np1],   ah, bh1[0], bh1[1]);
                mma_bf16(acc[2*np1+1], ah, bh1[2], bh1[3]);
                mma_bf16(acc[2*np0],   ah, bl0[0], bl0[1]);
                mma_bf16(acc[2*np0+1], ah, bl0[2], bl0[3]);
                mma_bf16(acc[2*np1],   ah, bl1[0], bl1[1]);
                mma_bf16(acc[2*np1+1], ah, bl1[2], bl1[3]);
                mma_bf16(acc[2*np0],   al, bh0[0], bh0[1]);
                mma_bf16(acc[2*np0+1], al, bh0[2], bh0[3]);
                mma_bf16(acc[2*np1],   al, bh1[0], bh1[1]);
                mma_bf16(acc[2*np1+1], al, bh1[2], bh1[3]);
            }
        }

        const float* bias = g ? bu : bq;
        __nv_bfloat16* Oh = g ? Uh : Qh;
        __nv_bfloat16* Ol = g ? Ul : Ql;
#pragma unroll
        for (int n = 0; n < 8; n++) {
            int d = wc * 64 + 8 * n + 2 * (lane & 3);
            float2 bb = *(const float2*)(bias + d);
            float v00 = acc[n][0] + bb.x, v01 = acc[n][1] + bb.y;
            float v10 = acc[n][2] + bb.x, v11 = acc[n][3] + bb.y;
            if (g) {
                v00 = fmaxf(v00, 0.f); v01 = fmaxf(v01, 0.f);
                v10 = fmaxf(v10, 0.f); v11 = fmaxf(v11, 0.f);
            }
            uint32_t h, l;
            split2(v00, v01, h, l);
            *(uint32_t*)(Oh + (size_t)(row0 + r0) * 128 + d) = h;
            *(uint32_t*)(Ol + (size_t)(row0 + r0) * 128 + d) = l;
            split2(v10, v11, h, l);
            *(uint32_t*)(Oh + (size_t)(row0 + r1) * 128 + d) = h;
            *(uint32_t*)(Ol + (size_t)(row0 + r1) * 128 + d) = l;
        }
    }
}

// =====================================================================
// embed (mma): R15 verbatim
// =====================================================================
__global__ __launch_bounds__(256, 2) void embed_mma_kernel(
    const float* __restrict__ A1, const float* __restrict__ A2,
    const __nv_bfloat16* __restrict__ WHb, const __nv_bfloat16* __restrict__ WLb,
    const float* __restrict__ b1, const float* __restrict__ b2,
    float* __restrict__ out1, float* __restrict__ out2) {
    extern __shared__ __align__(16) char sm[];
    const int tid = threadIdx.x;
    const int w   = tid >> 5, lane = tid & 31;
    const int row0 = blockIdx.x * 64;
    const int z = blockIdx.y;
    const uint32_t sb = smem_u32(sm);

    const float* A = z ? A2 : A1;
    const __nv_bfloat16* WH = WHb + z * 16384;
    const __nv_bfloat16* WL = WLb + z * 16384;
    const float* bias = z ? b2 : b1;
    float* out = z ? out2 : out1;

    for (int idx = tid; idx < 128 * 16; idx += 256) {
        int r = idx >> 4, c = idx & 15;
        uint32_t ro = (uint32_t)(r * IROWB + c * 16);
        cp16(sb + P_WH + ro, WH + (size_t)r * 128 + c * 8);
        cp16(sb + P_WL + ro, WL + (size_t)r * 128 + c * 8);
    }
    cp_commit();
    for (int idx = tid; idx < 64 * 32; idx += 256) {
        int r = idx >> 5, cq = idx & 31;
        uint32_t off = (uint32_t)(r * IROWB + cq * 8);
        uint32_t h0, l0, h1, l1;
        float4 av = *(const float4*)(A + (size_t)(row0 + r) * 128 + cq * 4);
        split2(av.x, av.y, h0, l0);
        split2(av.z, av.w, h1, l1);
        *(uint2*)(sm + P_XH + off) = make_uint2(h0, h1);
        *(uint2*)(sm + P_XL + off) = make_uint2(l0, l1);
    }
    cp_wait<0>();
    __syncthreads();

    const int wr = w >> 1, wc = w & 1;
    const uint32_t a_row  = 16 * wr + (lane & 15);
    const uint32_t a_cadd = (lane & 16) ? 16 : 0;
    const uint32_t u_radd = (uint32_t)(lane & 15);
    const uint32_t u_cadd = (lane & 16) ? 16 : 0;
    const int r0 = 16 * wr + (lane >> 2), r1 = r0 + 8;

    float acc[8][4];
#pragma unroll
    for (int n = 0; n < 8; n++)
#pragma unroll
        for (int c = 0; c < 4; c++) acc[n][c] = 0.f;

#pragma unroll
    for (int kt = 0; kt < 8; kt++) {
        uint32_t aoff = a_row * IROWB + kt * 32 + a_cadd;
        uint32_t ah[4], al[4];
        ldsm_x4(ah, sb + P_XH + aoff);
        ldsm_x4(al, sb + P_XL + aoff);
#pragma unroll
        for (int npp = 0; npp < 2; npp++) {
            int np0 = 2 * npp, np1 = 2 * npp + 1;
            uint32_t b0off = (16 * kt + u_radd) * IROWB + wc * 128 + np0 * 32 + u_cadd;
            uint32_t b1off = (16 * kt + u_radd) * IROWB + wc * 128 + np1 * 32 + u_cadd;
            uint32_t bh0[4], bl0[4], bh1[4], bl1[4];
            ldsm_x4t(bh0, sb + P_WH + b0off);
            ldsm_x4t(bl0, sb + P_WL + b0off);
            ldsm_x4t(bh1, sb + P_WH + b1off);
            ldsm_x4t(bl1, sb + P_WL + b1off);
            mma_bf16(acc[2*np0],   ah, bh0[0], bh0[1]);
            mma_bf16(acc[2*np0+1], ah, bh0[2], bh0[3]);
            mma_bf16(acc[2*np1],   ah, bh1[0], bh1[1]);
            mma_bf16(acc[2*np1+1], ah, bh1[2], bh1[3]);
            mma_bf16(acc[2*np0],   ah, bl0[0], bl0[1]);
            mma_bf16(acc[2*np0+1], ah, bl0[2], bl0[3]);
            mma_bf16(acc[2*np1],   ah, bl1[0], bl1[1]);
            mma_bf16(acc[2*np1+1], ah, bl1[2], bl1[3]);
            mma_bf16(acc[2*np0],   al, bh0[0], bh0[1]);
            mma_bf16(acc[2*np0+1], al, bh0[2], bh0[3]);
            mma_bf16(acc[2*np1],   al, bh1[0], bh1[1]);
            mma_bf16(acc[2*np1+1], al, bh1[2], bh1[3]);
        }
    }

#pragma unroll
    for (int n = 0; n < 8; n++) {
        int d = wc * 64 + 8 * n + 2 * (lane & 3);
        float2 bb = *(const float2*)(bias + d);
        float2 o0, o1;
        o0.x = fmaxf(acc[n][0] + bb.x, 0.f);
        o0.y = fmaxf(acc[n][1] + bb.y, 0.f);
        o1.x = fmaxf(acc[n][2] + bb.x, 0.f);
        o1.y = fmaxf(acc[n][3] + bb.y, 0.f);
        *(float2*)(out + (size_t)(row0 + r0) * 128 + d) = o0;
        *(float2*)(out + (size_t)(row0 + r1) * 128 + d) = o1;
    }
}

__device__ __forceinline__ float blk_reduce(float v, float* red, bool ismax) {
#pragma unroll
    for (int o = 16; o; o >>= 1) {
        float t = __shfl_xor_sync(0xffffffffu, v, o);
        v = ismax ? fmaxf(v, t) : v + t;
    }
    if ((threadIdx.x & 31) == 0) red[threadIdx.x >> 5] = v;
    __syncthreads();
    float r = red[0];
#pragma unroll
    for (int i = 1; i < (int)(blockDim.x >> 5); i++) r = ismax ? fmaxf(r, red[i]) : r + red[i];
    __syncthreads();
    return r;
}

// ---------------- pooling: one CTA per (batch, sequence) ----------------
__global__ __launch_bounds__(256) void pool_kernel(
    const float* __restrict__ Xg, const float* __restrict__ Yg,
    float* __restrict__ pooled) {
    __shared__ float w[1024];
    __shared__ float red[8];
    __shared__ float pp[256];
    const int tid = threadIdx.x;
    const int b   = blockIdx.x;
    const int s   = blockIdx.y;

    const float* S = (s ? Yg : Xg) + (size_t)b * SEQL * 128;
    for (int l = tid; l < SEQL; l += 256) {
        const float4* row = (const float4*)(S + (size_t)l*128);
        float acc = 0.f;
#pragma unroll
        for (int c = 0; c < 32; c++) {
            float4 v = row[c];
            acc += v.x*v.x + v.y*v.y + v.z*v.z + v.w*v.w;
        }
        w[l] = sqrtf(acc);
    }
    __syncthreads();
    float lm = -1e30f;
    for (int l = tid; l < SEQL; l += 256) lm = fmaxf(lm, w[l]);
    float mx = blk_reduce(lm, red, true);
    float ls = 0.f;
    for (int l = tid; l < SEQL; l += 256) { float e = expf(w[l] - mx); w[l] = e; ls += e; }
    float tot = blk_reduce(ls, red, false);
    float inv = 1.f / tot;

    int d = tid & 127, halfi = tid >> 7;
    float p = 0.f;
    for (int l = halfi; l < SEQL; l += 2) p += S[(size_t)l*128 + d] * w[l];
    pp[halfi*128 + d] = p;
    __syncthreads();
    if (tid < 128)
        pooled[(s * 16 + b) * 128 + tid] = (pp[tid] + pp[128 + tid]) * inv;
}

// ---------------- head ----------------
__global__ __launch_bounds__(128) void head_kernel(
    const float* __restrict__ pooled,
    const float* __restrict__ fc_w, const float* __restrict__ fc_b,
    const float* __restrict__ out_w, const float* __restrict__ out_b,
    float* __restrict__ out) {
    __shared__ float xp[128];
    __shared__ float yp[128];
    __shared__ float red[4];
    const int tid = threadIdx.x;
    const int b   = blockIdx.x;

    xp[tid] = pooled[b * 128 + tid];
    yp[tid] = pooled[(16 + b) * 128 + tid];
    __syncthreads();

    float h = fc_b[tid];
    for (int k2 = 0; k2 < 128; k2++) h += xp[k2] * fc_w[k2*128 + tid];
    for (int k2 = 0; k2 < 128; k2++) h += yp[k2] * fc_w[(128 + k2)*128 + tid];
    h = fmaxf(h, 0.f) * out_w[tid];
    float tot = blk_reduce(h, red, false);
    if (tid == 0) out[b] = 1.f / (1.f + expf(-(tot + out_b[0])));
}

// ---------------- launch ----------------
extern "C" void kernel_launch(void* const* d_in, const int* in_sizes, int n_in,
                              void* d_out, int out_size) {
    (void)in_sizes; (void)n_in; (void)out_size;
    const float* seq1  = (const float*)d_in[0];
    const float* seq2  = (const float*)d_in[1];
    const float* mask1 = (const float*)d_in[2];
    const float* mask2 = (const float*)d_in[3];
    const float* l1_w  = (const float*)d_in[4];
    const float* l1_b  = (const float*)d_in[5];
    const float* l2_w  = (const float*)d_in[6];
    const float* l2_b  = (const float*)d_in[7];
    const float* ln1_g = (const float*)d_in[8];
    const float* ln1_b = (const float*)d_in[9];
    const float* ln2_g = (const float*)d_in[10];
    const float* ln2_b = (const float*)d_in[11];
    const float* wq_w  = (const float*)d_in[12];
    const float* wq_b  = (const float*)d_in[13];
    const float* wk_w  = (const float*)d_in[14];
    const float* wk_b  = (const float*)d_in[15];
    const float* wvx_w = (const float*)d_in[16];
    const float* wvx_b = (const float*)d_in[17];
    const float* wvy_w = (const float*)d_in[18];
    const float* wvy_b = (const float*)d_in[19];
    const float* wx_w  = (const float*)d_in[20];
    const float* wx_b  = (const float*)d_in[21];
    const float* wy_w  = (const float*)d_in[22];
    const float* wy_b  = (const float*)d_in[23];
    const float* fc_w  = (const float*)d_in[24];
    const float* fc_b  = (const float*)d_in[25];
    const float* out_w = (const float*)d_in[26];
    const float* out_b = (const float*)d_in[27];

    float *x, *y, *vx, *vy, *vxm, *vym, *pool;
    __nv_bfloat16 *qh, *ql, *kh, *kl, *xuh, *xul, *yuh, *yul, *wbh, *wbl;
    cudaGetSymbolAddress((void**)&x,   g_x);
    cudaGetSymbolAddress((void**)&y,   g_y);
    cudaGetSymbolAddress((void**)&qh,  g_qh);
    cudaGetSymbolAddress((void**)&ql,  g_ql);
    cudaGetSymbolAddress((void**)&kh,  g_kh);
    cudaGetSymbolAddress((void**)&kl,  g_kl);
    cudaGetSymbolAddress((void**)&xuh, g_xuh);
    cudaGetSymbolAddress((void**)&xul, g_xul);
    cudaGetSymbolAddress((void**)&yuh, g_yuh);
    cudaGetSymbolAddress((void**)&yul, g_yul);
    cudaGetSymbolAddress((void**)&vx,  g_vx);
    cudaGetSymbolAddress((void**)&vy,  g_vy);
    cudaGetSymbolAddress((void**)&vxm, g_vxm);
    cudaGetSymbolAddress((void**)&vym, g_vym);
    cudaGetSymbolAddress((void**)&pool, g_pool);
    cudaGetSymbolAddress((void**)&wbh, g_wbh);
    cudaGetSymbolAddress((void**)&wbl, g_wbl);

    cudaFuncSetAttribute(embed_mma_kernel,    cudaFuncAttributeMaxDynamicSharedMemorySize, P_SMEM);
    cudaFuncSetAttribute(proj_mma_kernel,     cudaFuncAttributeMaxDynamicSharedMemorySize, P_SMEM);
    cudaFuncSetAttribute(interact_mma_kernel, cudaFuncAttributeMaxDynamicSharedMemorySize, I_SMEM);

    prep_w_kernel<<<dim3(32, 14), 256>>>(l1_w, l2_w, wq_w, wx_w, wk_w, wy_w, wbh, wbl);

    embed_mma_kernel<<<dim3(256, 2), 256, P_SMEM>>>(seq1, seq2, wbh, wbl,
                                                    l1_b, l2_b, x, y);

    for (int i = 0; i < 3; i++) {
        int base = 2 + i * 4;
        proj_mma_kernel<<<dim3(256, 2), 256, P_SMEM>>>(
            x, y,
            ln1_g + i*128, ln1_b + i*128, ln2_g + i*128, ln2_b + i*128,
            wbh + (base+0)*16384, wbl + (base+0)*16384, wq_b + i*128,
            wbh + (base+1)*16384, wbl + (base+1)*16384, wx_b + i*128,
            wvx_w + i*128, wvx_b + i,
            wbh + (base+2)*16384, wbl + (base+2)*16384, wk_b + i*128,
            wbh + (base+3)*16384, wbl + (base+3)*16384, wy_b + i*128,
            wvy_w + i*128, wvy_b + i,
            mask1, mask2,
            qh, ql, xuh, xul, kh, kl, yuh, yul,
            vx, vxm, vy, vym);
        interact_mma_kernel<<<dim3(16, 16, 2), 128, I_SMEM>>>(
            qh, ql, kh, kl, xuh, xul, yuh, yul, vxm, vy, vym, vx, x, y);
    }
    pool_kernel<<<dim3(16, 2), 256>>>(x, y, pool);
    head_kernel<<<16, 128>>>(pool, fc_w, fc_b, out_w, out_b, (float*)d_out);
}

// round 17
// speedup vs baseline: 1.4087x; 1.1151x over previous
#include <cuda_runtime.h>
#include <cuda_bf16.h>
#include <cstdint>
#include <math.h>

#define NROWS 16384        // B * L = 16 * 1024
#define SEQL  1024
#define SCALE_INV 0.08838834764831845f   // 1/sqrt(128)

// ---------------- persistent scratch ----------------
__device__ float g_x [NROWS*128];
__device__ float g_y [NROWS*128];
__device__ __nv_bfloat16 g_qh [NROWS*128];
__device__ __nv_bfloat16 g_kh [NROWS*128];
__device__ __nv_bfloat16 g_xuh[NROWS*128];
__device__ __nv_bfloat16 g_xul[NROWS*128];
__device__ __nv_bfloat16 g_yuh[NROWS*128];
__device__ __nv_bfloat16 g_yul[NROWS*128];
__device__ float g_vx [NROWS];
__device__ float g_vy [NROWS];
__device__ float g_vxm[NROWS];
__device__ float g_vym[NROWS];
__device__ float g_pool[2*16*128];
// preconverted weights: 14 matrices of 128x128
__device__ __align__(16) __nv_bfloat16 g_wbh[14*16384];
__device__ __align__(16) __nv_bfloat16 g_wbl[14*16384];

__device__ __forceinline__ float sigmoidf_fast(float x) {
    return __fdividef(1.f, 1.f + __expf(-x));
}

__device__ __forceinline__ uint32_t smem_u32(const void* p) {
    uint32_t a;
    asm("{ .reg .u64 t; cvta.to.shared.u64 t, %1; cvt.u32.u64 %0, t; }" : "=r"(a) : "l"(p));
    return a;
}

__device__ __forceinline__ uint32_t packbf(__nv_bfloat16 a, __nv_bfloat16 b) {
    __nv_bfloat162 t(a, b);
    return *reinterpret_cast<uint32_t*>(&t);
}

__device__ __forceinline__ void split2(float a, float b, uint32_t& hi, uint32_t& lo) {
    __nv_bfloat16 h0 = __float2bfloat16_rn(a), h1 = __float2bfloat16_rn(b);
    hi = packbf(h0, h1);
    lo = packbf(__float2bfloat16_rn(a - __bfloat162float(h0)),
                __float2bfloat16_rn(b - __bfloat162float(h1)));
}

__device__ __forceinline__ void ldsm_x4(uint32_t r[4], uint32_t addr) {
    asm volatile("ldmatrix.sync.aligned.m8n8.x4.shared.b16 {%0,%1,%2,%3}, [%4];"
                 : "=r"(r[0]), "=r"(r[1]), "=r"(r[2]), "=r"(r[3]) : "r"(addr));
}
__device__ __forceinline__ void ldsm_x4t(uint32_t r[4], uint32_t addr) {
    asm volatile("ldmatrix.sync.aligned.m8n8.x4.trans.shared.b16 {%0,%1,%2,%3}, [%4];"
                 : "=r"(r[0]), "=r"(r[1]), "=r"(r[2]), "=r"(r[3]) : "r"(addr));
}
__device__ __forceinline__ void mma_bf16(float c[4], const uint32_t a[4],
                                         uint32_t b0, uint32_t b1) {
    asm volatile(
        "mma.sync.aligned.m16n8k16.row.col.f32.bf16.bf16.f32 "
        "{%0,%1,%2,%3}, {%4,%5,%6,%7}, {%8,%9}, {%0,%1,%2,%3};"
        : "+f"(c[0]), "+f"(c[1]), "+f"(c[2]), "+f"(c[3])
        : "r"(a[0]), "r"(a[1]), "r"(a[2]), "r"(a[3]), "r"(b0), "r"(b1));
}

__device__ __forceinline__ void cp16(uint32_t saddr, const void* g) {
    asm volatile("cp.async.cg.shared.global [%0], [%1], 16;" :: "r"(saddr), "l"(g));
}
__device__ __forceinline__ void cp_commit() {
    asm volatile("cp.async.commit_group;" ::: "memory");
}
template<int N>
__device__ __forceinline__ void cp_wait() {
    asm volatile("cp.async.wait_group %0;" :: "n"(N) : "memory");
}

// ---- smem geometry ----
#define IROWB 272
#define QTILE (128 * IROWB)      // 34816
#define STILE (64 * IROWB)       // 17408
#define JTILE (32 * IROWB)       // 8704

// interact smem: 128-thr CTA, 64 i-rows (hi only), 32-row j-tiles (K hi-only).
#define O_QH  0
#define O_ST  STILE              // 17408
#define S_KH  0
#define S_UH  JTILE
#define S_UL  (2 * JTILE)
#define S_BS  (3 * JTILE)        // 32 floats
#define STAGE (3 * JTILE + 256)  // 26368
#define O_AS  (O_ST + 2 * STAGE) // 70144
#define I_SMEM (O_AS + 256)      // 70400  (2 CTAs/SM)

// proj / embed smem
#define P_XH  0
#define P_XL  STILE
#define P_WH  (2 * STILE)
#define P_WL  (P_WH + QTILE)
#define P_SMEM (P_WL + QTILE)    // 104448

// =====================================================================
// prep: convert 14 weight matrices fp32 -> bf16 hi/lo in gmem (once)
// =====================================================================
__global__ __launch_bounds__(256) void prep_w_kernel(
    const float* __restrict__ l1_w, const float* __restrict__ l2_w,
    const float* __restrict__ wq_w, const float* __restrict__ wx_w,
    const float* __restrict__ wk_w, const float* __restrict__ wy_w,
    __nv_bfloat16* __restrict__ WH, __nv_bfloat16* __restrict__ WL) {
    int m = blockIdx.y;
    const float* src;
    if (m == 0) src = l1_w;
    else if (m == 1) src = l2_w;
    else {
        int i = (m - 2) >> 2, r = (m - 2) & 3;
        src = (r == 0 ? wq_w : r == 1 ? wx_w : r == 2 ? wk_w : wy_w) + i * 16384;
    }
    int idx = blockIdx.x * 256 + threadIdx.x;
    float2 v = *(const float2*)(src + 2 * idx);
    uint32_t h, l;
    split2(v.x, v.y, h, l);
    *(uint32_t*)(WH + m * 16384 + 2 * idx) = h;
    *(uint32_t*)(WL + m * 16384 + 2 * idx) = l;
}

// =====================================================================
// interact: GEMM1 = Ah x Kh (pure bf16; both lo sides dropped -- sigmoid
// attenuated, measured ~1.2e-4 per side). GEMM2 full 3-term.
// 128 thr / 4 warps, 64 i-rows, 32-row j-tiles; 2 CTAs/SM.
// =====================================================================
__global__ __launch_bounds__(128, 2) void interact_mma_kernel(
    const __nv_bfloat16* __restrict__ qh, const __nv_bfloat16* __restrict__ kh,
    const __nv_bfloat16* __restrict__ xuh, const __nv_bfloat16* __restrict__ xul,
    const __nv_bfloat16* __restrict__ yuh, const __nv_bfloat16* __restrict__ yul,
    const float* __restrict__ vxm, const float* __restrict__ vy,
    const float* __restrict__ vym, const float* __restrict__ vx,
    float* __restrict__ xO, float* __restrict__ yO) {
    extern __shared__ __align__(16) char sm[];
    const int tid  = threadIdx.x;
    const int w    = tid >> 5, lane = tid & 31;
    const int b    = blockIdx.y;
    const int i0   = blockIdx.x * 64;
    const int z    = blockIdx.z;
    const uint32_t sb = smem_u32(sm);
    float* aSs = (float*)(sm + O_AS);

    const __nv_bfloat16* Ah = z ? kh  : qh;
    const __nv_bfloat16* Kh = z ? qh  : kh;
    const __nv_bfloat16* Uh = z ? xuh : yuh;
    const __nv_bfloat16* Ul = z ? xul : yul;
    const float* aS = z ? vym : vxm;
    const float* bS = z ? vx  : vy;
    float* Out      = z ? yO  : xO;

    const size_t rowbase = (size_t)(b * SEQL + i0) * 128;

    // A tile: 64 rows hi only + aS
    for (int i = tid; i < 64 * 16; i += 128) {
        int r = i >> 4, c = i & 15;
        uint32_t ro = (uint32_t)(r * IROWB + c * 16);
        size_t go = rowbase + (size_t)r * 128 + c * 8;
        cp16(sb + O_QH + ro, Ah + go);
    }
    if (tid < 16) cp16(sb + O_AS + tid * 16, aS + b * SEQL + i0 + tid * 4);

#define ISSUE_STAGE(JT, BUF) do { \
        const size_t jb = (size_t)(b * SEQL + (JT) * 32) * 128; \
        uint32_t st = sb + O_ST + (BUF) * STAGE; \
        for (int i = tid; i < 32 * 16; i += 128) { \
            int r = i >> 4, c = i & 15; \
            uint32_t ro = (uint32_t)(r * IROWB + c * 16); \
            size_t go = jb + (size_t)r * 128 + c * 8; \
            cp16(st + S_KH + ro, Kh + go); \
            cp16(st + S_UH + ro, Uh + go); \
            cp16(st + S_UL + ro, Ul + go); \
        } \
        if (tid < 8) cp16(st + S_BS + tid * 16, bS + b * SEQL + (JT) * 32 + tid * 4); \
    } while (0)

    ISSUE_STAGE(0, 0);
    cp_commit();

    float oacc[16][4];
#pragma unroll
    for (int n = 0; n < 16; n++)
#pragma unroll
        for (int c = 0; c < 4; c++) oacc[n][c] = 0.f;

    const uint32_t a_row  = 16 * w + (lane & 15);
    const uint32_t a_cadd = (lane & 16) ? 16 : 0;
    const uint32_t b_rsub = (uint32_t)(((lane & 16) ? 8 : 0) + (lane & 7));
    const uint32_t b_cadd = (lane & 8) ? 16 : 0;
    const uint32_t u_radd = (uint32_t)(lane & 15);
    const uint32_t u_cadd = (lane & 16) ? 16 : 0;

    uint32_t ahr[8][4];

    for (int jt = 0; jt < 32; jt++) {
        if (jt + 1 < 32) {
            ISSUE_STAGE(jt + 1, (jt + 1) & 1);
            cp_commit();
            cp_wait<1>();
        } else {
            cp_wait<0>();
        }
        __syncthreads();

        if (jt == 0) {
#pragma unroll
            for (int kt = 0; kt < 8; kt++) {
                uint32_t aoff = a_row * IROWB + kt * 32 + a_cadd;
                ldsm_x4(ahr[kt], sb + O_QH + aoff);
            }
        }

        const uint32_t st = sb + O_ST + (jt & 1) * STAGE;
        const float* bSs = (const float*)(sm + O_ST + (jt & 1) * STAGE + S_BS);

        // ---- GEMM1: S[16 x 32] = Ah @ Kh^T (pure bf16) ----
        float sacc[4][4];
#pragma unroll
        for (int n = 0; n < 4; n++)
#pragma unroll
            for (int c = 0; c < 4; c++) sacc[n][c] = 0.f;

#pragma unroll
        for (int kt = 0; kt < 8; kt++) {
            uint32_t b0off = b_rsub * IROWB + kt * 32 + b_cadd;
            uint32_t b1off = (16 + b_rsub) * IROWB + kt * 32 + b_cadd;
            uint32_t bh0[4], bh1[4];
            ldsm_x4(bh0, st + S_KH + b0off);
            ldsm_x4(bh1, st + S_KH + b1off);
            mma_bf16(sacc[0], ahr[kt], bh0[0], bh0[1]);
            mma_bf16(sacc[1], ahr[kt], bh0[2], bh0[3]);
            mma_bf16(sacc[2], ahr[kt], bh1[0], bh1[1]);
            mma_bf16(sacc[3], ahr[kt], bh1[2], bh1[3]);
        }

        uint32_t ph[4][2], pl[4][2];
#pragma unroll
        for (int n = 0; n < 4; n++) {
            int j0 = 8 * n + 2 * (lane & 3);
            float2 bv = *(const float2*)(bSs + j0);
            float p00 = sigmoidf_fast(sacc[n][0] * SCALE_INV) * bv.x;
            float p01 = sigmoidf_fast(sacc[n][1] * SCALE_INV) * bv.y;
            float p10 = sigmoidf_fast(sacc[n][2] * SCALE_INV) * bv.x;
            float p11 = sigmoidf_fast(sacc[n][3] * SCALE_INV) * bv.y;
            split2(p00, p01, ph[n][0], pl[n][0]);
            split2(p10, p11, ph[n][1], pl[n][1]);
        }

        // ---- GEMM2: O += (Ph+Pl) @ (Uh+Ul)  (full 3-term) ----
#pragma unroll
        for (int kt = 0; kt < 2; kt++) {
            uint32_t ah[4] = { ph[2*kt][0], ph[2*kt][1], ph[2*kt+1][0], ph[2*kt+1][1] };
            uint32_t al[4] = { pl[2*kt][0], pl[2*kt][1], pl[2*kt+1][0], pl[2*kt+1][1] };
#pragma unroll
            for (int npp = 0; npp < 4; npp++) {
                int np0 = 2 * npp, np1 = 2 * npp + 1;
                uint32_t u0off = (16 * kt + u_radd) * IROWB + np0 * 32 + u_cadd;
                uint32_t u1off = (16 * kt + u_radd) * IROWB + np1 * 32 + u_cadd;
                uint32_t uh0[4], ul0[4], uh1[4], ul1[4];
                ldsm_x4t(uh0, st + S_UH + u0off);
                ldsm_x4t(ul0, st + S_UL + u0off);
                ldsm_x4t(uh1, st + S_UH + u1off);
                ldsm_x4t(ul1, st + S_UL + u1off);
                mma_bf16(oacc[2*np0],   ah, uh0[0], uh0[1]);
                mma_bf16(oacc[2*np0+1], ah, uh0[2], uh0[3]);
                mma_bf16(oacc[2*np1],   ah, uh1[0], uh1[1]);
                mma_bf16(oacc[2*np1+1], ah, uh1[2], uh1[3]);
                mma_bf16(oacc[2*np0],   ah, ul0[0], ul0[1]);
                mma_bf16(oacc[2*np0+1], ah, ul0[2], ul0[3]);
                mma_bf16(oacc[2*np1],   ah, ul1[0], ul1[1]);
                mma_bf16(oacc[2*np1+1], ah, ul1[2], ul1[3]);
                mma_bf16(oacc[2*np0],   al, uh0[0], uh0[1]);
                mma_bf16(oacc[2*np0+1], al, uh0[2], uh0[3]);
                mma_bf16(oacc[2*np1],   al, uh1[0], uh1[1]);
                mma_bf16(oacc[2*np1+1], al, uh1[2], uh1[3]);
            }
        }
        __syncthreads();
    }
#undef ISSUE_STAGE

    {
        int r0 = 16 * w + (lane >> 2), r1 = r0 + 8;
        float av0 = aSs[r0], av1 = aSs[r1];
        float* Ob = Out + rowbase;
#pragma unroll
        for (int n = 0; n < 16; n++) {
            int d = 8 * n + 2 * (lane & 3);
            float2 o0 = *(float2*)(Ob + (size_t)r0 * 128 + d);
            o0.x += av0 * oacc[n][0];
            o0.y += av0 * oacc[n][1];
            *(float2*)(Ob + (size_t)r0 * 128 + d) = o0;
            float2 o1 = *(float2*)(Ob + (size_t)r1 * 128 + d);
            o1.x += av1 * oacc[n][2];
            o1.y += av1 * oacc[n][3];
            *(float2*)(Ob + (size_t)r1 * 128 + d) = o1;
        }
    }
}

// =====================================================================
// proj (mma) with fused LN; Wq prefetched before LN. Q/K outputs hi-only.
// =====================================================================
__global__ __launch_bounds__(256, 2) void proj_mma_kernel(
    float* __restrict__ X1, float* __restrict__ X2,
    const float* __restrict__ lng1, const float* __restrict__ lnb1,
    const float* __restrict__ lng2, const float* __restrict__ lnb2,
    const __nv_bfloat16* __restrict__ WqH1, const __nv_bfloat16* __restrict__ WqL1,
    const float* __restrict__ bq1,
    const __nv_bfloat16* __restrict__ WuH1, const __nv_bfloat16* __restrict__ WuL1,
    const float* __restrict__ bu1,
    const float* __restrict__ wv1, const float* __restrict__ bv1,
    const __nv_bfloat16* __restrict__ WqH2, const __nv_bfloat16* __restrict__ WqL2,
    const float* __restrict__ bq2,
    const __nv_bfloat16* __restrict__ WuH2, const __nv_bfloat16* __restrict__ WuL2,
    const float* __restrict__ bu2,
    const float* __restrict__ wv2, const float* __restrict__ bv2,
    const float* __restrict__ mask1, const float* __restrict__ mask2,
    __nv_bfloat16* __restrict__ qh,
    __nv_bfloat16* __restrict__ xuh, __nv_bfloat16* __restrict__ xul,
    __nv_bfloat16* __restrict__ kh,
    __nv_bfloat16* __restrict__ yuh, __nv_bfloat16* __restrict__ yul,
    float* __restrict__ vx, float* __restrict__ vxm,
    float* __restrict__ vy, float* __restrict__ vym) {
    extern __shared__ __align__(16) char sm[];
    const int tid = threadIdx.x;
    const int w   = tid >> 5, lane = tid & 31;
    const int row0 = blockIdx.x * 64;
    const int z = blockIdx.y;
    const uint32_t sb = smem_u32(sm);

    float* X = z ? X2 : X1;
    const float* lng = z ? lng2 : lng1;
    const float* lnb = z ? lnb2 : lnb1;
    const __nv_bfloat16* WqH = z ? WqH2 : WqH1;
    const __nv_bfloat16* WqL = z ? WqL2 : WqL1;
    const __nv_bfloat16* WuH = z ? WuH2 : WuH1;
    const __nv_bfloat16* WuL = z ? WuL2 : WuL1;
    const float* bq = z ? bq2 : bq1;
    const float* bu = z ? bu2 : bu1;
    const float* wv = z ? wv2 : wv1;
    const float* bv = z ? bv2 : bv1;
    const float* mask = z ? mask2 : mask1;
    __nv_bfloat16* Qh = z ? kh : qh;
    __nv_bfloat16* Uh = z ? yuh : xuh;
    __nv_bfloat16* Ul = z ? yul : xul;
    float* Vs  = z ? vy : vx;
    float* Vsm = z ? vym : vxm;

    for (int idx = tid; idx < 128 * 16; idx += 256) {
        int r = idx >> 4, c = idx & 15;
        uint32_t ro = (uint32_t)(r * IROWB + c * 16);
        cp16(sb + P_WH + ro, WqH + (size_t)r * 128 + c * 8);
        cp16(sb + P_WL + ro, WqL + (size_t)r * 128 + c * 8);
    }
    cp_commit();

    {
        float4 gg  = ((const float4*)lng)[lane];
        float4 bb4 = ((const float4*)lnb)[lane];
        float4 wv4 = ((const float4*)wv)[lane];
        float bv0 = bv[0];
        for (int rr = 0; rr < 8; rr++) {
            int r  = 8 * w + rr;
            int gr = row0 + r;
            float4* Xr = (float4*)(X + (size_t)gr * 128);
            float4 v = Xr[lane];
            float s = v.x + v.y + v.z + v.w;
#pragma unroll
            for (int o = 16; o; o >>= 1) s += __shfl_xor_sync(0xffffffffu, s, o);
            float m = s * (1.f/128.f);
            float d0 = v.x - m, d1 = v.y - m, d2 = v.z - m, d3 = v.w - m;
            float q = d0*d0 + d1*d1 + d2*d2 + d3*d3;
#pragma unroll
            for (int o = 16; o; o >>= 1) q += __shfl_xor_sync(0xffffffffu, q, o);
            float inv = rsqrtf(q * (1.f/128.f) + 1e-5f);
            v.x = d0*inv*gg.x + bb4.x;
            v.y = d1*inv*gg.y + bb4.y;
            v.z = d2*inv*gg.z + bb4.z;
            v.w = d3*inv*gg.w + bb4.w;
            Xr[lane] = v;

            float gs = v.x*wv4.x + v.y*wv4.y + v.z*wv4.z + v.w*wv4.w;
#pragma unroll
            for (int o = 16; o; o >>= 1) gs += __shfl_xor_sync(0xffffffffu, gs, o);
            if (lane == 0) {
                float vv = fmaxf(gs + bv0, 0.f);
                Vs[gr]  = vv;
                Vsm[gr] = vv * mask[gr];
            }

            uint32_t h0, l0, h1, l1;
            split2(v.x, v.y, h0, l0);
            split2(v.z, v.w, h1, l1);
            *(uint2*)(sm + P_XH + (uint32_t)(r * IROWB + lane * 8)) = make_uint2(h0, h1);
            *(uint2*)(sm + P_XL + (uint32_t)(r * IROWB + lane * 8)) = make_uint2(l0, l1);
        }
    }

    const int wr = w >> 1, wc = w & 1;
    const uint32_t a_row  = 16 * wr + (lane & 15);
    const uint32_t a_cadd = (lane & 16) ? 16 : 0;
    const uint32_t u_radd = (uint32_t)(lane & 15);
    const uint32_t u_cadd = (lane & 16) ? 16 : 0;
    const int r0 = 16 * wr + (lane >> 2), r1 = r0 + 8;

    for (int g = 0; g < 2; g++) {
        if (g == 1) {
            __syncthreads();
            for (int idx = tid; idx < 128 * 16; idx += 256) {
                int r = idx >> 4, c = idx & 15;
                uint32_t ro = (uint32_t)(r * IROWB + c * 16);
                cp16(sb + P_WH + ro, WuH + (size_t)r * 128 + c * 8);
                cp16(sb + P_WL + ro, WuL + (size_t)r * 128 + c * 8);
            }
            cp_commit();
        }
        cp_wait<0>();
        __syncthreads();

        float acc[8][4];
#pragma unroll
        for (int n = 0; n < 8; n++)
#pragma unroll
            for (int c = 0; c < 4; c++) acc[n][c] = 0.f;

#pragma unroll
        for (int kt = 0; kt < 8; kt++) {
            uint32_t aoff = a_row * IROWB + kt * 32 + a_cadd;
            uint32_t ah[4], al[4];
            ldsm_x4(ah, sb + P_XH + aoff);
            ldsm_x4(al, sb + P_XL + aoff);
#pragma unroll
            for (int npp = 0; npp < 2; npp++) {
                int np0 = 2 * npp, np1 = 2 * npp + 1;
                uint32_t b0off = (16 * kt + u_radd) * IROWB + wc * 128 + np0 * 32 + u_cadd;
                uint32_t b1off = (16 * kt + u_radd) * IROWB + wc * 128 + np1 * 32 + u_cadd;
                uint32_t bh0[4], bl0[4], bh1[4], bl1[4];
                ldsm_x4t(bh0, sb + P_WH + b0off);
                ldsm_x4t(bl0, sb + P_WL + b0off);
                ldsm_x4t(bh1, sb + P_WH + b1off);
                ldsm_x4t(bl1, sb + P_WL + b1off);
                mma_bf16(acc[2*np0],   ah, bh0[0], bh0[1]);
                mma_bf16(acc[2*np0+1], ah, bh0[2], bh0[3]);
                mma_bf16(acc[2*np1],   ah, bh1[0], bh1[1]);
                mma_bf16(acc[2*np1+1], ah, bh1[2], bh1[3]);
                mma_bf16(acc[2*np0],   ah, bl0[0], bl0[1]);
                mma_bf16(acc[2*np0+1], ah, bl0[2], bl0[3]);
                mma_bf16(acc[2*np1],   ah, bl1[0], bl1[1]);
                mma_bf16(acc[2*np1+1], ah, bl1[2], bl1[3]);
                mma_bf16(acc[2*np0],   al, bh0[0], bh0[1]);
                mma_bf16(acc[2*np0+1], al, bh0[2], bh0[3]);
                mma_bf16(acc[2*np1],   al, bh1[0], bh1[1]);
                mma_bf16(acc[2*np1+1], al, bh1[2], bh1[3]);
            }
        }

        const float* bias = g ? bu : bq;
#pragma unroll
        for (int n = 0; n < 8; n++) {
            int d = wc * 64 + 8 * n + 2 * (lane & 3);
            float2 bb = *(const float2*)(bias + d);
            float v00 = acc[n][0] + bb.x, v01 = acc[n][1] + bb.y;
            float v10 = acc[n][2] + bb.x, v11 = acc[n][3] + bb.y;
            uint32_t h, l;
            if (g) {
                v00 = fmaxf(v00, 0.f); v01 = fmaxf(v01, 0.f);
                v10 = fmaxf(v10, 0.f); v11 = fmaxf(v11, 0.f);
                split2(v00, v01, h, l);
                *(uint32_t*)(Uh + (size_t)(row0 + r0) * 128 + d) = h;
                *(uint32_t*)(Ul + (size_t)(row0 + r0) * 128 + d) = l;
                split2(v10, v11, h, l);
                *(uint32_t*)(Uh + (size_t)(row0 + r1) * 128 + d) = h;
                *(uint32_t*)(Ul + (size_t)(row0 + r1) * 128 + d) = l;
            } else {
                // Q/K path: hi only (interact GEMM1 is pure bf16)
                split2(v00, v01, h, l);
                *(uint32_t*)(Qh + (size_t)(row0 + r0) * 128 + d) = h;
                split2(v10, v11, h, l);
                *(uint32_t*)(Qh + (size_t)(row0 + r1) * 128 + d) = h;
            }
        }
    }
}

// =====================================================================
// embed (mma): unchanged (64-row CTAs, preconverted W, 2 CTAs/SM)
// =====================================================================
__global__ __launch_bounds__(256, 2) void embed_mma_kernel(
    const float* __restrict__ A1, const float* __restrict__ A2,
    const __nv_bfloat16* __restrict__ WHb, const __nv_bfloat16* __restrict__ WLb,
    const float* __restrict__ b1, const float* __restrict__ b2,
    float* __restrict__ out1, float* __restrict__ out2) {
    extern __shared__ __align__(16) char sm[];
    const int tid = threadIdx.x;
    const int w   = tid >> 5, lane = tid & 31;
    const int row0 = blockIdx.x * 64;
    const int z = blockIdx.y;
    const uint32_t sb = smem_u32(sm);

    const float* A = z ? A2 : A1;
    const __nv_bfloat16* WH = WHb + z * 16384;
    const __nv_bfloat16* WL = WLb + z * 16384;
    const float* bias = z ? b2 : b1;
    float* out = z ? out2 : out1;

    for (int idx = tid; idx < 128 * 16; idx += 256) {
        int r = idx >> 4, c = idx & 15;
        uint32_t ro = (uint32_t)(r * IROWB + c * 16);
        cp16(sb + P_WH + ro, WH + (size_t)r * 128 + c * 8);
        cp16(sb + P_WL + ro, WL + (size_t)r * 128 + c * 8);
    }
    cp_commit();
    for (int idx = tid; idx < 64 * 32; idx += 256) {
        int r = idx >> 5, cq = idx & 31;
        uint32_t off = (uint32_t)(r * IROWB + cq * 8);
        uint32_t h0, l0, h1, l1;
        float4 av = *(const float4*)(A + (size_t)(row0 + r) * 128 + cq * 4);
        split2(av.x, av.y, h0, l0);
        split2(av.z, av.w, h1, l1);
        *(uint2*)(sm + P_XH + off) = make_uint2(h0, h1);
        *(uint2*)(sm + P_XL + off) = make_uint2(l0, l1);
    }
    cp_wait<0>();
    __syncthreads();

    const int wr = w >> 1, wc = w & 1;
    const uint32_t a_row  = 16 * wr + (lane & 15);
    const uint32_t a_cadd = (lane & 16) ? 16 : 0;
    const uint32_t u_radd = (uint32_t)(lane & 15);
    const uint32_t u_cadd = (lane & 16) ? 16 : 0;
    const int r0 = 16 * wr + (lane >> 2), r1 = r0 + 8;

    float acc[8][4];
#pragma unroll
    for (int n = 0; n < 8; n++)
#pragma unroll
        for (int c = 0; c < 4; c++) acc[n][c] = 0.f;

#pragma unroll
    for (int kt = 0; kt < 8; kt++) {
        uint32_t aoff = a_row * IROWB + kt * 32 + a_cadd;
        uint32_t ah[4], al[4];
        ldsm_x4(ah, sb + P_XH + aoff);
        ldsm_x4(al, sb + P_XL + aoff);
#pragma unroll
        for (int npp = 0; npp < 2; npp++) {
            int np0 = 2 * npp, np1 = 2 * npp + 1;
            uint32_t b0off = (16 * kt + u_radd) * IROWB + wc * 128 + np0 * 32 + u_cadd;
            uint32_t b1off = (16 * kt + u_radd) * IROWB + wc * 128 + np1 * 32 + u_cadd;
            uint32_t bh0[4], bl0[4], bh1[4], bl1[4];
            ldsm_x4t(bh0, sb + P_WH + b0off);
            ldsm_x4t(bl0, sb + P_WL + b0off);
            ldsm_x4t(bh1, sb + P_WH + b1off);
            ldsm_x4t(bl1, sb + P_WL + b1off);
            mma_bf16(acc[2*np0],   ah, bh0[0], bh0[1]);
            mma_bf16(acc[2*np0+1], ah, bh0[2], bh0[3]);
            mma_bf16(acc[2*np1],   ah, bh1[0], bh1[1]);
            mma_bf16(acc[2*np1+1], ah, bh1[2], bh1[3]);
            mma_bf16(acc[2*np0],   ah, bl0[0], bl0[1]);
            mma_bf16(acc[2*np0+1], ah, bl0[2], bl0[3]);
            mma_bf16(acc[2*np1],   ah, bl1[0], bl1[1]);
            mma_bf16(acc[2*np1+1], ah, bl1[2], bl1[3]);
            mma_bf16(acc[2*np0],   al, bh0[0], bh0[1]);
            mma_bf16(acc[2*np0+1], al, bh0[2], bh0[3]);
            mma_bf16(acc[2*np1],   al, bh1[0], bh1[1]);
            mma_bf16(acc[2*np1+1], al, bh1[2], bh1[3]);
        }
    }

#pragma unroll
    for (int n = 0; n < 8; n++) {
        int d = wc * 64 + 8 * n + 2 * (lane & 3);
        float2 bb = *(const float2*)(bias + d);
        float2 o0, o1;
        o0.x = fmaxf(acc[n][0] + bb.x, 0.f);
        o0.y = fmaxf(acc[n][1] + bb.y, 0.f);
        o1.x = fmaxf(acc[n][2] + bb.x, 0.f);
        o1.y = fmaxf(acc[n][3] + bb.y, 0.f);
        *(float2*)(out + (size_t)(row0 + r0) * 128 + d) = o0;
        *(float2*)(out + (size_t)(row0 + r1) * 128 + d) = o1;
    }
}

__device__ __forceinline__ float blk_reduce(float v, float* red, bool ismax) {
#pragma unroll
    for (int o = 16; o; o >>= 1) {
        float t = __shfl_xor_sync(0xffffffffu, v, o);
        v = ismax ? fmaxf(v, t) : v + t;
    }
    if ((threadIdx.x & 31) == 0) red[threadIdx.x >> 5] = v;
    __syncthreads();
    float r = red[0];
#pragma unroll
    for (int i = 1; i < (int)(blockDim.x >> 5); i++) r = ismax ? fmaxf(r, red[i]) : r + red[i];
    __syncthreads();
    return r;
}

// ---------------- pooling: one CTA per (batch, sequence) ----------------
__global__ __launch_bounds__(256) void pool_kernel(
    const float* __restrict__ Xg, const float* __restrict__ Yg,
    float* __restrict__ pooled) {
    __shared__ float w[1024];
    __shared__ float red[8];
    __shared__ float pp[256];
    const int tid = threadIdx.x;
    const int b   = blockIdx.x;
    const int s   = blockIdx.y;

    const float* S = (s ? Yg : Xg) + (size_t)b * SEQL * 128;
    for (int l = tid; l < SEQL; l += 256) {
        const float4* row = (const float4*)(S + (size_t)l*128);
        float acc = 0.f;
#pragma unroll
        for (int c = 0; c < 32; c++) {
            float4 v = row[c];
            acc += v.x*v.x + v.y*v.y + v.z*v.z + v.w*v.w;
        }
        w[l] = sqrtf(acc);
    }
    __syncthreads();
    float lm = -1e30f;
    for (int l = tid; l < SEQL; l += 256) lm = fmaxf(lm, w[l]);
    float mx = blk_reduce(lm, red, true);
    float ls = 0.f;
    for (int l = tid; l < SEQL; l += 256) { float e = expf(w[l] - mx); w[l] = e; ls += e; }
    float tot = blk_reduce(ls, red, false);
    float inv = 1.f / tot;

    int d = tid & 127, halfi = tid >> 7;
    float p = 0.f;
    for (int l = halfi; l < SEQL; l += 2) p += S[(size_t)l*128 + d] * w[l];
    pp[halfi*128 + d] = p;
    __syncthreads();
    if (tid < 128)
        pooled[(s * 16 + b) * 128 + tid] = (pp[tid] + pp[128 + tid]) * inv;
}

// ---------------- head ----------------
__global__ __launch_bounds__(128) void head_kernel(
    const float* __restrict__ pooled,
    const float* __restrict__ fc_w, const float* __restrict__ fc_b,
    const float* __restrict__ out_w, const float* __restrict__ out_b,
    float* __restrict__ out) {
    __shared__ float xp[128];
    __shared__ float yp[128];
    __shared__ float red[4];
    const int tid = threadIdx.x;
    const int b   = blockIdx.x;

    xp[tid] = pooled[b * 128 + tid];
    yp[tid] = pooled[(16 + b) * 128 + tid];
    __syncthreads();

    float h = fc_b[tid];
    for (int k2 = 0; k2 < 128; k2++) h += xp[k2] * fc_w[k2*128 + tid];
    for (int k2 = 0; k2 < 128; k2++) h += yp[k2] * fc_w[(128 + k2)*128 + tid];
    h = fmaxf(h, 0.f) * out_w[tid];
    float tot = blk_reduce(h, red, false);
    if (tid == 0) out[b] = 1.f / (1.f + expf(-(tot + out_b[0])));
}

// ---------------- launch ----------------
extern "C" void kernel_launch(void* const* d_in, const int* in_sizes, int n_in,
                              void* d_out, int out_size) {
    (void)in_sizes; (void)n_in; (void)out_size;
    const float* seq1  = (const float*)d_in[0];
    const float* seq2  = (const float*)d_in[1];
    const float* mask1 = (const float*)d_in[2];
    const float* mask2 = (const float*)d_in[3];
    const float* l1_w  = (const float*)d_in[4];
    const float* l1_b  = (const float*)d_in[5];
    const float* l2_w  = (const float*)d_in[6];
    const float* l2_b  = (const float*)d_in[7];
    const float* ln1_g = (const float*)d_in[8];
    const float* ln1_b = (const float*)d_in[9];
    const float* ln2_g = (const float*)d_in[10];
    const float* ln2_b = (const float*)d_in[11];
    const float* wq_w  = (const float*)d_in[12];
    const float* wq_b  = (const float*)d_in[13];
    const float* wk_w  = (const float*)d_in[14];
    const float* wk_b  = (const float*)d_in[15];
    const float* wvx_w = (const float*)d_in[16];
    const float* wvx_b = (const float*)d_in[17];
    const float* wvy_w = (const float*)d_in[18];
    const float* wvy_b = (const float*)d_in[19];
    const float* wx_w  = (const float*)d_in[20];
    const float* wx_b  = (const float*)d_in[21];
    const float* wy_w  = (const float*)d_in[22];
    const float* wy_b  = (const float*)d_in[23];
    const float* fc_w  = (const float*)d_in[24];
    const float* fc_b  = (const float*)d_in[25];
    const float* out_w = (const float*)d_in[26];
    const float* out_b = (const float*)d_in[27];

    float *x, *y, *vx, *vy, *vxm, *vym, *pool;
    __nv_bfloat16 *qh, *kh, *xuh, *xul, *yuh, *yul, *wbh, *wbl;
    cudaGetSymbolAddress((void**)&x,   g_x);
    cudaGetSymbolAddress((void**)&y,   g_y);
    cudaGetSymbolAddress((void**)&qh,  g_qh);
    cudaGetSymbolAddress((void**)&kh,  g_kh);
    cudaGetSymbolAddress((void**)&xuh, g_xuh);
    cudaGetSymbolAddress((void**)&xul, g_xul);
    cudaGetSymbolAddress((void**)&yuh, g_yuh);
    cudaGetSymbolAddress((void**)&yul, g_yul);
    cudaGetSymbolAddress((void**)&vx,  g_vx);
    cudaGetSymbolAddress((void**)&vy,  g_vy);
    cudaGetSymbolAddress((void**)&vxm, g_vxm);
    cudaGetSymbolAddress((void**)&vym, g_vym);
    cudaGetSymbolAddress((void**)&pool, g_pool);
    cudaGetSymbolAddress((void**)&wbh, g_wbh);
    cudaGetSymbolAddress((void**)&wbl, g_wbl);

    cudaFuncSetAttribute(embed_mma_kernel,    cudaFuncAttributeMaxDynamicSharedMemorySize, P_SMEM);
    cudaFuncSetAttribute(proj_mma_kernel,     cudaFuncAttributeMaxDynamicSharedMemorySize, P_SMEM);
    cudaFuncSetAttribute(interact_mma_kernel, cudaFuncAttributeMaxDynamicSharedMemorySize, I_SMEM);

    prep_w_kernel<<<dim3(32, 14), 256>>>(l1_w, l2_w, wq_w, wx_w, wk_w, wy_w, wbh, wbl);

    embed_mma_kernel<<<dim3(256, 2), 256, P_SMEM>>>(seq1, seq2, wbh, wbl,
                                                    l1_b, l2_b, x, y);

    for (int i = 0; i < 3; i++) {
        int base = 2 + i * 4;
        proj_mma_kernel<<<dim3(256, 2), 256, P_SMEM>>>(
            x, y,
            ln1_g + i*128, ln1_b + i*128, ln2_g + i*128, ln2_b + i*128,
            wbh + (base+0)*16384, wbl + (base+0)*16384, wq_b + i*128,
            wbh + (base+1)*16384, wbl + (base+1)*16384, wx_b + i*128,
            wvx_w + i*128, wvx_b + i,
            wbh + (base+2)*16384, wbl + (base+2)*16384, wk_b + i*128,
            wbh + (base+3)*16384, wbl + (base+3)*16384, wy_b + i*128,
            wvy_w + i*128, wvy_b + i,
            mask1, mask2,
            qh, xuh, xul, kh, yuh, yul,
            vx, vxm, vy, vym);
        interact_mma_kernel<<<dim3(16, 16, 2), 128, I_SMEM>>>(
            qh, kh, xuh, xul, yuh, yul, vxm, vy, vym, vx, x, y);
    }
    pool_kernel<<<dim3(16, 2), 256>>>(x, y, pool);
    head_kernel<<<16, 128>>>(pool, fc_w, fc_b, out_w, out_b, (float*)d_out);
}